// round 5
// baseline (speedup 1.0000x reference)
#include <cuda_runtime.h>
#include <cuda_bf16.h>
#include <math.h>

// Problem constants
#define B_    16
#define T_    64
#define H_    1024
#define D_    2048      // 2H
#define EMB_  512
#define MO_   1024      // maxout units
#define V_    32000
#define G3_   3072      // 3H
#define CAT_  3584      // H + EMB + D
#define NBLK  148       // persistent grid (<= SM count => co-resident)

// ---------------- scratch (device globals) ----------------------------------
__device__ float g_hemb[B_ * T_ * T_];          // h @ W_h + b_h      [b*T+t][j]
__device__ float g_Hih [B_ * T_ * G3_];         // h @ W_ih + b_ih
__device__ float g_s   [B_ * H_];               // GRU state
__device__ float g_E   [T_ * B_ * T_];          // attention weights [i][b][t]
__device__ float g_gpart[9 * B_ * G3_];         // gate partials [q][b][col]
__device__ float g_alignpart[4][B_][T_];        // s@W_s partials [kc2][b][j]
__device__ float g_cat [T_ * B_ * CAT_];        // [s_new | y_emb | c]
__device__ float g_tt  [T_ * B_ * 2 * MO_];     // t_tilde
__device__ unsigned g_barcnt;
__device__ volatile unsigned g_barsense;

// ---------------------------------------------------------------------------
__global__ void init_kernel() {
    int i = blockIdx.x * blockDim.x + threadIdx.x;
    if (i < B_ * H_) g_s[i] = 0.0f;
    if (i < 4 * B_ * T_) ((float*)g_alignpart)[i] = 0.0f;
    if (i == 0) { g_barcnt = 0; g_barsense = 0; }
}

// ---------------- tf32 tensor-core GEMM, 128x128x16, double-buffered --------
__device__ __forceinline__ unsigned f2tf(float f) {
    unsigned r; asm("cvt.rna.tf32.f32 %0, %1;" : "=r"(r) : "f"(f)); return r;
}

template <bool PERMUTE, bool AMAX>
__global__ __launch_bounds__(256, 2)
void mma_gemm_kernel(const float* __restrict__ A, int lda,
                     const float* __restrict__ Bm, int ldb,
                     float* __restrict__ C, int ldc,
                     const float* __restrict__ bias, int K, int ncols)
{
    __shared__ unsigned As[2][128][20];   // m-major, pad 20
    __shared__ unsigned Bs[2][16][136];   // k-major, pad 136

    const int tid = threadIdx.x;
    const int wid = tid >> 5, lane = tid & 31;
    const int wm = wid & 3, wn = wid >> 2;          // warps 4(M) x 2(N)
    const int m0 = blockIdx.y * 128, n0 = blockIdx.x * 128;

    const int arow = tid >> 2;                      // 0..63 (+64)
    const int acol = (tid & 3) * 4;
    const int brow = tid >> 5;                      // 0..7 (+8)
    const int bcol = lane * 4;
    int colb = n0 + bcol;
    if (colb > ncols - 4) colb = ncols - 4;         // clamp (ncols mult of 4)

    float acc[2][8][4];
#pragma unroll
    for (int mi = 0; mi < 2; mi++)
#pragma unroll
        for (int ni = 0; ni < 8; ni++)
#pragma unroll
            for (int u = 0; u < 4; u++) acc[mi][ni][u] = 0.0f;

    float4 a0v, a1v, b0v, b1v;

    auto loadA1 = [&](int row, int k0) -> float4 {
        float4 u = *reinterpret_cast<const float4*>(&A[(size_t)row * lda + k0 + acol]);
        if (AMAX) {
            float4 v = *reinterpret_cast<const float4*>(&A[(size_t)row * lda + MO_ + k0 + acol]);
            u.x = fmaxf(u.x, v.x); u.y = fmaxf(u.y, v.y);
            u.z = fmaxf(u.z, v.z); u.w = fmaxf(u.w, v.w);
        }
        return u;
    };
    auto loadT = [&](int k0) {
        a0v = loadA1(m0 + arow, k0);
        a1v = loadA1(m0 + arow + 64, k0);
        b0v = *reinterpret_cast<const float4*>(&Bm[(size_t)(k0 + brow) * ldb + colb]);
        b1v = *reinterpret_cast<const float4*>(&Bm[(size_t)(k0 + brow + 8) * ldb + colb]);
    };
    auto stage = [&](int p) {
        As[p][arow][acol + 0] = f2tf(a0v.x); As[p][arow][acol + 1] = f2tf(a0v.y);
        As[p][arow][acol + 2] = f2tf(a0v.z); As[p][arow][acol + 3] = f2tf(a0v.w);
        As[p][arow + 64][acol + 0] = f2tf(a1v.x); As[p][arow + 64][acol + 1] = f2tf(a1v.y);
        As[p][arow + 64][acol + 2] = f2tf(a1v.z); As[p][arow + 64][acol + 3] = f2tf(a1v.w);
        Bs[p][brow][bcol + 0] = f2tf(b0v.x); Bs[p][brow][bcol + 1] = f2tf(b0v.y);
        Bs[p][brow][bcol + 2] = f2tf(b0v.z); Bs[p][brow][bcol + 3] = f2tf(b0v.w);
        Bs[p][brow + 8][bcol + 0] = f2tf(b1v.x); Bs[p][brow + 8][bcol + 1] = f2tf(b1v.y);
        Bs[p][brow + 8][bcol + 2] = f2tf(b1v.z); Bs[p][brow + 8][bcol + 3] = f2tf(b1v.w);
    };
    auto compute = [&](int p) {
#pragma unroll
        for (int k8 = 0; k8 < 2; k8++) {
            const int kb = k8 * 8;
            unsigned af[2][4], bf[8][2];
#pragma unroll
            for (int mi = 0; mi < 2; mi++) {
                int r = wm * 32 + mi * 16 + (lane >> 2);
                af[mi][0] = As[p][r][kb + (lane & 3)];
                af[mi][1] = As[p][r + 8][kb + (lane & 3)];
                af[mi][2] = As[p][r][kb + (lane & 3) + 4];
                af[mi][3] = As[p][r + 8][kb + (lane & 3) + 4];
            }
#pragma unroll
            for (int ni = 0; ni < 8; ni++) {
                int c = wn * 64 + ni * 8 + (lane >> 2);
                bf[ni][0] = Bs[p][kb + (lane & 3)][c];
                bf[ni][1] = Bs[p][kb + (lane & 3) + 4][c];
            }
#pragma unroll
            for (int mi = 0; mi < 2; mi++)
#pragma unroll
                for (int ni = 0; ni < 8; ni++) {
                    asm volatile(
                        "mma.sync.aligned.m16n8k8.row.col.f32.tf32.tf32.f32 "
                        "{%0,%1,%2,%3}, {%4,%5,%6,%7}, {%8,%9}, {%0,%1,%2,%3};"
                        : "+f"(acc[mi][ni][0]), "+f"(acc[mi][ni][1]),
                          "+f"(acc[mi][ni][2]), "+f"(acc[mi][ni][3])
                        : "r"(af[mi][0]), "r"(af[mi][1]), "r"(af[mi][2]), "r"(af[mi][3]),
                          "r"(bf[ni][0]), "r"(bf[ni][1]));
                }
        }
    };

    loadT(0); stage(0); __syncthreads();
    int buf = 0;
    for (int k0 = 16; k0 < K; k0 += 16) {
        loadT(k0);
        compute(buf);
        stage(buf ^ 1);
        __syncthreads();
        buf ^= 1;
    }
    compute(buf);

#pragma unroll
    for (int mi = 0; mi < 2; mi++) {
        int r = m0 + wm * 32 + mi * 16 + (lane >> 2);
        int r0 = PERMUTE ? ((r & (B_ - 1)) * T_ + (r >> 4)) : r;
        int r8 = r + 8;
        int r1 = PERMUTE ? ((r8 & (B_ - 1)) * T_ + (r8 >> 4)) : r8;
#pragma unroll
        for (int ni = 0; ni < 8; ni++) {
            int c = n0 + wn * 64 + ni * 8 + (lane & 3) * 2;
            if (c < ncols) {
                float bc0 = bias[c], bc1 = bias[c + 1];
                C[(size_t)r0 * ldc + c]     = acc[mi][ni][0] + bc0;
                C[(size_t)r0 * ldc + c + 1] = acc[mi][ni][1] + bc1;
                C[(size_t)r1 * ldc + c]     = acc[mi][ni][2] + bc0;
                C[(size_t)r1 * ldc + c + 1] = acc[mi][ni][3] + bc1;
            }
        }
    }
}

// ---------------- grid-wide sense barrier -----------------------------------
__device__ __forceinline__ void gsync(unsigned target) {
    __syncthreads();
    if (threadIdx.x == 0) {
        __threadfence();
        unsigned old = atomicAdd(&g_barcnt, 1);
        if (old == NBLK - 1) {
            g_barcnt = 0;
            __threadfence();
            g_barsense = target;
        } else {
            while (g_barsense < target) { }
        }
        __threadfence();
    }
    __syncthreads();
}

// ---------------- persistent recurrence kernel ------------------------------
// Phase A (432 tasks): q<8 -> s@W_hh partials (fp32);
//                      q==8 -> softmax(tanh(align+bs+hemb)) then e@Hih (fp32).
// Phase B (64 tasks):  gather partials, GRU pointwise, s@W_s partials.
__global__ __launch_bounds__(256, 1)
void recur_kernel(const float* __restrict__ Whh,
                  const float* __restrict__ Ws,
                  const float* __restrict__ bs,
                  const float* __restrict__ bhh)
{
    __shared__ float s_sh[16][128];
    __shared__ float part[4][16][64];
    __shared__ float e_sh[16][65];
    __shared__ float s2[256];
    __shared__ float redp[4][64];

    const int tid = threadIdx.x;
    const int bid = blockIdx.x;
    unsigned bar = 0;

    for (int i = 0; i < T_; i++) {
        // ---------------- phase A -------------------------------------------
        for (int task = bid; task < 432; task += NBLK) {
            const int q = task / 48, cchunk = task - q * 48;
            if (q < 8) {
                const int col = tid & 63, ks = tid >> 6;
                const int gcol = cchunk * 64 + col;
                for (int r = tid; r < 16 * 128; r += 256)
                    s_sh[r >> 7][r & 127] = g_s[(r >> 7) * H_ + q * 128 + (r & 127)];
                __syncthreads();
                float acc[16];
#pragma unroll
                for (int b = 0; b < 16; b++) acc[b] = 0.0f;
                const int kbase = q * 128 + ks * 32, koff = ks * 32;
#pragma unroll 16
                for (int kk = 0; kk < 32; kk++) {
                    float w = Whh[(size_t)(kbase + kk) * G3_ + gcol];
#pragma unroll
                    for (int b = 0; b < 16; b++) acc[b] += w * s_sh[b][koff + kk];
                }
#pragma unroll
                for (int b = 0; b < 16; b++) part[ks][b][col] = acc[b];
                __syncthreads();
#pragma unroll
                for (int bb = 0; bb < 4; bb++) {
                    int b = ks * 4 + bb;
                    g_gpart[(size_t)(q * 16 + b) * G3_ + gcol] =
                        part[0][b][col] + part[1][b][col] +
                        part[2][b][col] + part[3][b][col];
                }
                __syncthreads();
            } else {
                // softmax (recomputed per task; identical arithmetic)
                {
                    const int lane = tid & 31;
                    const int b2 = (tid >> 5) * 2 + (lane >> 4);
                    const int j0 = (lane & 15) * 4;
                    float a[4];
#pragma unroll
                    for (int u = 0; u < 4; u++) {
                        int j = j0 + u;
                        float v = bs[j] + g_hemb[(b2 * T_ + i) * T_ + j];
#pragma unroll
                        for (int kc = 0; kc < 4; kc++) v += g_alignpart[kc][b2][j];
                        a[u] = tanhf(v);
                    }
                    float m = fmaxf(fmaxf(a[0], a[1]), fmaxf(a[2], a[3]));
#pragma unroll
                    for (int o = 8; o > 0; o >>= 1)
                        m = fmaxf(m, __shfl_xor_sync(0xffffffffu, m, o));
                    float ex[4], ssum = 0.0f;
#pragma unroll
                    for (int u = 0; u < 4; u++) { ex[u] = __expf(a[u] - m); ssum += ex[u]; }
#pragma unroll
                    for (int o = 8; o > 0; o >>= 1)
                        ssum += __shfl_xor_sync(0xffffffffu, ssum, o);
                    float inv = 1.0f / ssum;
#pragma unroll
                    for (int u = 0; u < 4; u++) {
                        e_sh[b2][j0 + u] = ex[u] * inv;
                        if (cchunk == 0) g_E[(i * B_ + b2) * T_ + j0 + u] = ex[u] * inv;
                    }
                }
                __syncthreads();
                // gi = e @ Hih (fp32), float4 col groups, coalesced rows
                const int b = tid >> 4, cg = tid & 15;
                const int colb = cchunk * 64 + cg * 4;
                float a0 = 0, a1 = 0, a2 = 0, a3 = 0;
                const float* Hrow = g_Hih + (size_t)(b * T_) * G3_ + colb;
#pragma unroll 8
                for (int t = 0; t < 64; t++) {
                    float e = e_sh[b][t];
                    float4 p = *reinterpret_cast<const float4*>(Hrow + (size_t)t * G3_);
                    a0 += e * p.x; a1 += e * p.y; a2 += e * p.z; a3 += e * p.w;
                }
                float4 o4 = make_float4(a0, a1, a2, a3);
                *reinterpret_cast<float4*>(
                    &g_gpart[(size_t)(8 * 16 + b) * G3_ + colb]) = o4;
                __syncthreads();
            }
        }
        gsync(++bar);
        // ---------------- phase B -------------------------------------------
        for (int task = bid; task < 64; task += NBLK) {
            const int b = task >> 2, kc2 = task & 3;
            const int k = kc2 * 256 + tid;

            float gr = bhh[k], gz = bhh[H_ + k], hn = bhh[2 * H_ + k];
#pragma unroll
            for (int q = 0; q < 8; q++) {
                const float* P = g_gpart + (size_t)(q * 16 + b) * G3_;
                gr += P[k]; gz += P[H_ + k]; hn += P[2 * H_ + k];
            }
            const float* P8 = g_gpart + (size_t)(8 * 16 + b) * G3_;
            gr += P8[k]; gz += P8[H_ + k];
            float inn = P8[2 * H_ + k];

            float r = 1.0f / (1.0f + __expf(-gr));
            float z = 1.0f / (1.0f + __expf(-gz));
            float n = tanhf(inn + r * hn);
            float sold = g_s[b * H_ + k];
            float snew = (1.0f - z) * n + z * sold;
            g_s[b * H_ + k] = snew;
            g_cat[(size_t)(i * B_ + b) * CAT_ + k] = snew;

            s2[tid] = snew;
            __syncthreads();
            const int j = tid & 63, sub = tid >> 6;
            float a = 0.0f;
#pragma unroll 8
            for (int kk = 0; kk < 64; kk++)
                a += s2[sub * 64 + kk] * Ws[(size_t)(kc2 * 256 + sub * 64 + kk) * T_ + j];
            redp[sub][j] = a;
            __syncthreads();
            if (tid < 64)
                g_alignpart[kc2][b][tid] =
                    redp[0][tid] + redp[1][tid] + redp[2][tid] + redp[3][tid];
            __syncthreads();
        }
        gsync(++bar);
    }
}

// ---------------- batched context: c[i,b,:] = e[i,b,:] @ h[b] ---------------
__global__ __launch_bounds__(128)
void ctx_kernel(const float* __restrict__ h)
{
    const int b = blockIdx.x, dc = blockIdx.y, tid = threadIdx.x;
    __shared__ float sh_h[T_][128];
    __shared__ float e_sh[T_];
    const int dbase = dc * 128;
    for (int t = 0; t < T_; t++)
        sh_h[t][tid] = h[(size_t)(b * T_ + t) * D_ + dbase + tid];
    __syncthreads();
    for (int i = 0; i < T_; i++) {
        if (tid < 64) e_sh[tid] = g_E[(i * B_ + b) * T_ + tid];
        __syncthreads();
        float acc = 0.0f;
#pragma unroll 8
        for (int t = 0; t < T_; t++) acc += e_sh[t] * sh_h[t][tid];
        g_cat[(size_t)(i * B_ + b) * CAT_ + H_ + EMB_ + dbase + tid] = acc;
        __syncthreads();
    }
}

// ---------------------------------------------------------------------------
extern "C" void kernel_launch(void* const* d_in, const int* in_sizes, int n_in,
                              void* d_out, int out_size)
{
    (void)in_sizes; (void)n_in; (void)out_size;
    const float* h     = (const float*)d_in[0];
    const float* W_h   = (const float*)d_in[1];
    const float* b_h   = (const float*)d_in[2];
    const float* W_s   = (const float*)d_in[3];
    const float* b_s   = (const float*)d_in[4];
    const float* W_ih  = (const float*)d_in[5];
    const float* b_ih  = (const float*)d_in[6];
    const float* W_hh  = (const float*)d_in[7];
    const float* b_hh  = (const float*)d_in[8];
    const float* W_emb = (const float*)d_in[9];
    const float* b_emb = (const float*)d_in[10];
    const float* W_t   = (const float*)d_in[11];
    const float* b_t   = (const float*)d_in[12];
    const float* W_out = (const float*)d_in[13];
    const float* b_out = (const float*)d_in[14];
    float* out = (float*)d_out;

    float *p_hemb, *p_Hih, *p_cat, *p_tt;
    cudaGetSymbolAddress((void**)&p_hemb, g_hemb);
    cudaGetSymbolAddress((void**)&p_Hih,  g_Hih);
    cudaGetSymbolAddress((void**)&p_cat,  g_cat);
    cudaGetSymbolAddress((void**)&p_tt,   g_tt);

    init_kernel<<<(B_ * H_ + 255) / 256, 256>>>();

    // Precompute: h_emb = h@W_h+b_h (N=64, guarded) ; Hih = h@W_ih+b_ih
    mma_gemm_kernel<false, false><<<dim3(1, (B_ * T_) / 128), 256>>>(
        h, D_, W_h, T_, p_hemb, T_, b_h, D_, T_);
    mma_gemm_kernel<false, false><<<dim3(G3_ / 128, (B_ * T_) / 128), 256>>>(
        h, D_, W_ih, G3_, p_Hih, G3_, b_ih, D_, G3_);

    // Entire 64-step recurrence in ONE persistent cooperative kernel
    recur_kernel<<<NBLK, 256>>>(W_hh, W_s, b_s, b_hh);

    // Batched epilogue
    ctx_kernel<<<dim3(B_, D_ / 128), 128>>>(h);
    mma_gemm_kernel<false, false><<<dim3(EMB_ / 128, (T_ * B_) / 128), 256>>>(
        p_cat, CAT_, W_emb, EMB_, p_cat + H_, CAT_, b_emb, H_, EMB_);
    mma_gemm_kernel<false, false><<<dim3(2 * MO_ / 128, (T_ * B_) / 128), 256>>>(
        p_cat, CAT_, W_t, 2 * MO_, p_tt, 2 * MO_, b_t, CAT_, 2 * MO_);
    // Vocab GEMM with maxout fused into the A-operand load
    mma_gemm_kernel<true, true><<<dim3(V_ / 128, (T_ * B_) / 128), 256>>>(
        p_tt, 2 * MO_, W_out, V_, out, V_, b_out, MO_, V_);
}

// round 6
// speedup vs baseline: 1.0152x; 1.0152x over previous
#include <cuda_runtime.h>
#include <cuda_bf16.h>
#include <math.h>

// Problem constants
#define B_    16
#define T_    64
#define H_    1024
#define D_    2048      // 2H
#define EMB_  512
#define MO_   1024      // maxout units
#define V_    32000
#define G3_   3072      // 3H
#define CAT_  3584      // H + EMB + D
#define NBLK  148       // persistent grid (<= SM count => co-resident)

// ---------------- scratch (device globals) ----------------------------------
__device__ float g_hemb[B_ * T_ * T_];          // h @ W_h + b_h      [b*T+t][j]
__device__ float g_Hih [B_ * T_ * G3_];         // h @ W_ih + b_ih
__device__ float g_s   [B_ * H_];               // GRU state
__device__ float g_E   [T_ * B_ * T_];          // attention weights [i][b][t]
__device__ float g_gpart[9 * B_ * G3_];         // gate partials [q][b][col]
__device__ float g_alignpart[4][B_][T_];        // s@W_s partials [kc2][b][j]
__device__ float g_cat [T_ * B_ * CAT_];        // [s_new | y_emb | c]
__device__ float g_tt  [T_ * B_ * 2 * MO_];     // t_tilde
__device__ unsigned g_barcnt;
__device__ volatile unsigned g_barsense;

// ---------------------------------------------------------------------------
__global__ void init_kernel() {
    int i = blockIdx.x * blockDim.x + threadIdx.x;
    if (i < B_ * H_) g_s[i] = 0.0f;
    if (i < 4 * B_ * T_) ((float*)g_alignpart)[i] = 0.0f;
    if (i == 0) { g_barcnt = 0; g_barsense = 0; }
}

// ---------------- tf32 helpers ----------------------------------------------
__device__ __forceinline__ unsigned f2tf(float f) {
    unsigned r; asm("cvt.rna.tf32.f32 %0, %1;" : "=r"(r) : "f"(f)); return r;
}

// ---------------- tf32 tensor-core GEMM, 128x128x16, double-buffered --------
template <bool PERMUTE, bool AMAX>
__global__ __launch_bounds__(256, 2)
void mma_gemm_kernel(const float* __restrict__ A, int lda,
                     const float* __restrict__ Bm, int ldb,
                     float* __restrict__ C, int ldc,
                     const float* __restrict__ bias, int K, int ncols)
{
    __shared__ unsigned As[2][128][20];   // m-major, pad 20
    __shared__ unsigned Bs[2][16][136];   // k-major, pad 136

    const int tid = threadIdx.x;
    const int wid = tid >> 5, lane = tid & 31;
    const int wm = wid & 3, wn = wid >> 2;          // warps 4(M) x 2(N)
    const int m0 = blockIdx.y * 128, n0 = blockIdx.x * 128;

    const int arow = tid >> 2;                      // 0..63 (+64)
    const int acol = (tid & 3) * 4;
    const int brow = tid >> 5;                      // 0..7 (+8)
    const int bcol = lane * 4;
    int colb = n0 + bcol;
    if (colb > ncols - 4) colb = ncols - 4;         // clamp (ncols mult of 4)

    float acc[2][8][4];
#pragma unroll
    for (int mi = 0; mi < 2; mi++)
#pragma unroll
        for (int ni = 0; ni < 8; ni++)
#pragma unroll
            for (int u = 0; u < 4; u++) acc[mi][ni][u] = 0.0f;

    float4 a0v, a1v, b0v, b1v;

    auto loadA1 = [&](int row, int k0) -> float4 {
        float4 u = *reinterpret_cast<const float4*>(&A[(size_t)row * lda + k0 + acol]);
        if (AMAX) {
            float4 v = *reinterpret_cast<const float4*>(&A[(size_t)row * lda + MO_ + k0 + acol]);
            u.x = fmaxf(u.x, v.x); u.y = fmaxf(u.y, v.y);
            u.z = fmaxf(u.z, v.z); u.w = fmaxf(u.w, v.w);
        }
        return u;
    };
    auto loadT = [&](int k0) {
        a0v = loadA1(m0 + arow, k0);
        a1v = loadA1(m0 + arow + 64, k0);
        b0v = *reinterpret_cast<const float4*>(&Bm[(size_t)(k0 + brow) * ldb + colb]);
        b1v = *reinterpret_cast<const float4*>(&Bm[(size_t)(k0 + brow + 8) * ldb + colb]);
    };
    auto stage = [&](int p) {
        As[p][arow][acol + 0] = f2tf(a0v.x); As[p][arow][acol + 1] = f2tf(a0v.y);
        As[p][arow][acol + 2] = f2tf(a0v.z); As[p][arow][acol + 3] = f2tf(a0v.w);
        As[p][arow + 64][acol + 0] = f2tf(a1v.x); As[p][arow + 64][acol + 1] = f2tf(a1v.y);
        As[p][arow + 64][acol + 2] = f2tf(a1v.z); As[p][arow + 64][acol + 3] = f2tf(a1v.w);
        Bs[p][brow][bcol + 0] = f2tf(b0v.x); Bs[p][brow][bcol + 1] = f2tf(b0v.y);
        Bs[p][brow][bcol + 2] = f2tf(b0v.z); Bs[p][brow][bcol + 3] = f2tf(b0v.w);
        Bs[p][brow + 8][bcol + 0] = f2tf(b1v.x); Bs[p][brow + 8][bcol + 1] = f2tf(b1v.y);
        Bs[p][brow + 8][bcol + 2] = f2tf(b1v.z); Bs[p][brow + 8][bcol + 3] = f2tf(b1v.w);
    };
    auto compute = [&](int p) {
#pragma unroll
        for (int k8 = 0; k8 < 2; k8++) {
            const int kb = k8 * 8;
            unsigned af[2][4], bf[8][2];
#pragma unroll
            for (int mi = 0; mi < 2; mi++) {
                int r = wm * 32 + mi * 16 + (lane >> 2);
                af[mi][0] = As[p][r][kb + (lane & 3)];
                af[mi][1] = As[p][r + 8][kb + (lane & 3)];
                af[mi][2] = As[p][r][kb + (lane & 3) + 4];
                af[mi][3] = As[p][r + 8][kb + (lane & 3) + 4];
            }
#pragma unroll
            for (int ni = 0; ni < 8; ni++) {
                int c = wn * 64 + ni * 8 + (lane >> 2);
                bf[ni][0] = Bs[p][kb + (lane & 3)][c];
                bf[ni][1] = Bs[p][kb + (lane & 3) + 4][c];
            }
#pragma unroll
            for (int mi = 0; mi < 2; mi++)
#pragma unroll
                for (int ni = 0; ni < 8; ni++) {
                    asm volatile(
                        "mma.sync.aligned.m16n8k8.row.col.f32.tf32.tf32.f32 "
                        "{%0,%1,%2,%3}, {%4,%5,%6,%7}, {%8,%9}, {%0,%1,%2,%3};"
                        : "+f"(acc[mi][ni][0]), "+f"(acc[mi][ni][1]),
                          "+f"(acc[mi][ni][2]), "+f"(acc[mi][ni][3])
                        : "r"(af[mi][0]), "r"(af[mi][1]), "r"(af[mi][2]), "r"(af[mi][3]),
                          "r"(bf[ni][0]), "r"(bf[ni][1]));
                }
        }
    };

    loadT(0); stage(0); __syncthreads();
    int buf = 0;
    for (int k0 = 16; k0 < K; k0 += 16) {
        loadT(k0);
        compute(buf);
        stage(buf ^ 1);
        __syncthreads();
        buf ^= 1;
    }
    compute(buf);

#pragma unroll
    for (int mi = 0; mi < 2; mi++) {
        int r = m0 + wm * 32 + mi * 16 + (lane >> 2);
        int r0 = PERMUTE ? ((r & (B_ - 1)) * T_ + (r >> 4)) : r;
        int r8 = r + 8;
        int r1 = PERMUTE ? ((r8 & (B_ - 1)) * T_ + (r8 >> 4)) : r8;
#pragma unroll
        for (int ni = 0; ni < 8; ni++) {
            int c = n0 + wn * 64 + ni * 8 + (lane & 3) * 2;
            if (c < ncols) {
                float bc0 = bias[c], bc1 = bias[c + 1];
                C[(size_t)r0 * ldc + c]     = acc[mi][ni][0] + bc0;
                C[(size_t)r0 * ldc + c + 1] = acc[mi][ni][1] + bc1;
                C[(size_t)r1 * ldc + c]     = acc[mi][ni][2] + bc0;
                C[(size_t)r1 * ldc + c + 1] = acc[mi][ni][3] + bc1;
            }
        }
    }
}

// ---------------- grid-wide sense barrier -----------------------------------
__device__ __forceinline__ void gsync(unsigned target) {
    __syncthreads();
    if (threadIdx.x == 0) {
        __threadfence();
        unsigned old = atomicAdd(&g_barcnt, 1);
        if (old == NBLK - 1) {
            g_barcnt = 0;
            __threadfence();
            g_barsense = target;
        } else {
            while (g_barsense < target) { }
        }
        __threadfence();
    }
    __syncthreads();
}

// ---------------- persistent recurrence kernel (tensor-core phase A) --------
// Phase A, 480 tasks:
//   task < 384: mma task (q = task/48 in 0..7 K-slices of 128,
//               c = task%48 col-chunk of 64): partial s@W_hh -> g_gpart[q]
//   task >= 384: c32 = task-384 in 0..95: softmax + e@Hih (32 cols) -> slot 8
// Phase B, 64 tasks: gather 9 partials, GRU pointwise, s@W_s partials.
__global__ __launch_bounds__(256, 1)
void recur_kernel(const float* __restrict__ Whh,
                  const float* __restrict__ Ws,
                  const float* __restrict__ bs,
                  const float* __restrict__ bhh)
{
    __shared__ union {
        struct { unsigned a[16][136]; unsigned b[128][72]; } m;  // mma tiles
        float part[16][66];                                      // k-reduce
        float e[16][65];                                         // attn weights
        struct { float s2[256]; float redp[4][64]; } pb;         // phase B
    } sm;

    const int tid = threadIdx.x;
    const int bid = blockIdx.x;
    const int lane = tid & 31, wid = tid >> 5;
    unsigned bar = 0;

    for (int i = 0; i < T_; i++) {
        // ---------------- phase A -------------------------------------------
        for (int task = bid; task < 480; task += NBLK) {
            if (task < 384) {
                const int q = task / 48, c = task - q * 48;
                // stage A: s[16][128] (tf32)
                {
                    const int b = tid >> 4, c8 = (tid & 15) * 8;
                    const float* src = &g_s[b * H_ + q * 128 + c8];
                    float4 v0 = *reinterpret_cast<const float4*>(src);
                    float4 v1 = *reinterpret_cast<const float4*>(src + 4);
                    sm.m.a[b][c8 + 0] = f2tf(v0.x); sm.m.a[b][c8 + 1] = f2tf(v0.y);
                    sm.m.a[b][c8 + 2] = f2tf(v0.z); sm.m.a[b][c8 + 3] = f2tf(v0.w);
                    sm.m.a[b][c8 + 4] = f2tf(v1.x); sm.m.a[b][c8 + 5] = f2tf(v1.y);
                    sm.m.a[b][c8 + 6] = f2tf(v1.z); sm.m.a[b][c8 + 7] = f2tf(v1.w);
                }
                // stage B: Whh[q*128 .. +127][c*64 .. +63] (tf32)
                {
                    const int rr = tid >> 4, c4 = (tid & 15) * 4;
#pragma unroll
                    for (int p = 0; p < 8; p++) {
                        int row = p * 16 + rr;
                        float4 v = *reinterpret_cast<const float4*>(
                            &Whh[(size_t)(q * 128 + row) * G3_ + c * 64 + c4]);
                        sm.m.b[row][c4 + 0] = f2tf(v.x);
                        sm.m.b[row][c4 + 1] = f2tf(v.y);
                        sm.m.b[row][c4 + 2] = f2tf(v.z);
                        sm.m.b[row][c4 + 3] = f2tf(v.w);
                    }
                }
                __syncthreads();
                const int wk = wid >> 2, wn = wid & 3;   // 2 k-slices x 4 n-slices
                float acc[2][4];
#pragma unroll
                for (int ni = 0; ni < 2; ni++)
#pragma unroll
                    for (int u = 0; u < 4; u++) acc[ni][u] = 0.0f;
#pragma unroll
                for (int k8 = 0; k8 < 8; k8++) {
                    const int kb = wk * 64 + k8 * 8;
                    unsigned af[4];
                    af[0] = sm.m.a[lane >> 2][kb + (lane & 3)];
                    af[1] = sm.m.a[(lane >> 2) + 8][kb + (lane & 3)];
                    af[2] = sm.m.a[lane >> 2][kb + (lane & 3) + 4];
                    af[3] = sm.m.a[(lane >> 2) + 8][kb + (lane & 3) + 4];
#pragma unroll
                    for (int ni = 0; ni < 2; ni++) {
                        const int cc = wn * 16 + ni * 8 + (lane >> 2);
                        unsigned bf0 = sm.m.b[kb + (lane & 3)][cc];
                        unsigned bf1 = sm.m.b[kb + (lane & 3) + 4][cc];
                        asm volatile(
                            "mma.sync.aligned.m16n8k8.row.col.f32.tf32.tf32.f32 "
                            "{%0,%1,%2,%3}, {%4,%5,%6,%7}, {%8,%9}, {%0,%1,%2,%3};"
                            : "+f"(acc[ni][0]), "+f"(acc[ni][1]),
                              "+f"(acc[ni][2]), "+f"(acc[ni][3])
                            : "r"(af[0]), "r"(af[1]), "r"(af[2]), "r"(af[3]),
                              "r"(bf0), "r"(bf1));
                    }
                }
                __syncthreads();        // done reading sm.m
                if (wk == 1) {
#pragma unroll
                    for (int ni = 0; ni < 2; ni++) {
                        const int r = lane >> 2, cc = wn * 16 + ni * 8 + (lane & 3) * 2;
                        sm.part[r][cc]         = acc[ni][0];
                        sm.part[r][cc + 1]     = acc[ni][1];
                        sm.part[r + 8][cc]     = acc[ni][2];
                        sm.part[r + 8][cc + 1] = acc[ni][3];
                    }
                }
                __syncthreads();
                if (wk == 0) {
#pragma unroll
                    for (int ni = 0; ni < 2; ni++) {
                        const int r = lane >> 2, cc = wn * 16 + ni * 8 + (lane & 3) * 2;
                        const int gc = c * 64 + cc;
                        g_gpart[(size_t)(q * 16 + r) * G3_ + gc] =
                            acc[ni][0] + sm.part[r][cc];
                        g_gpart[(size_t)(q * 16 + r) * G3_ + gc + 1] =
                            acc[ni][1] + sm.part[r][cc + 1];
                        g_gpart[(size_t)(q * 16 + r + 8) * G3_ + gc] =
                            acc[ni][2] + sm.part[r + 8][cc];
                        g_gpart[(size_t)(q * 16 + r + 8) * G3_ + gc + 1] =
                            acc[ni][3] + sm.part[r + 8][cc + 1];
                    }
                }
                __syncthreads();
            } else {
                const int c32 = task - 384;     // 0..95, 32 cols each
                // softmax (recomputed per task; identical arithmetic)
                {
                    const int b2 = (tid >> 5) * 2 + (lane >> 4);
                    const int j0 = (lane & 15) * 4;
                    float a[4];
#pragma unroll
                    for (int u = 0; u < 4; u++) {
                        int j = j0 + u;
                        float v = bs[j] + g_hemb[(b2 * T_ + i) * T_ + j];
#pragma unroll
                        for (int kc = 0; kc < 4; kc++) v += g_alignpart[kc][b2][j];
                        a[u] = tanhf(v);
                    }
                    float m = fmaxf(fmaxf(a[0], a[1]), fmaxf(a[2], a[3]));
#pragma unroll
                    for (int o = 8; o > 0; o >>= 1)
                        m = fmaxf(m, __shfl_xor_sync(0xffffffffu, m, o));
                    float ex[4], ssum = 0.0f;
#pragma unroll
                    for (int u = 0; u < 4; u++) { ex[u] = __expf(a[u] - m); ssum += ex[u]; }
#pragma unroll
                    for (int o = 8; o > 0; o >>= 1)
                        ssum += __shfl_xor_sync(0xffffffffu, ssum, o);
                    float inv = 1.0f / ssum;
#pragma unroll
                    for (int u = 0; u < 4; u++) {
                        sm.e[b2][j0 + u] = ex[u] * inv;
                        if (c32 == 0) g_E[(i * B_ + b2) * T_ + j0 + u] = ex[u] * inv;
                    }
                }
                __syncthreads();
                // gi = e @ Hih (fp32), float2 col groups, coalesced rows
                const int b = tid >> 4;
                const int colb = c32 * 32 + (tid & 15) * 2;
                float a0 = 0.0f, a1 = 0.0f;
                const float* Hrow = g_Hih + (size_t)(b * T_) * G3_ + colb;
#pragma unroll 8
                for (int t = 0; t < 64; t++) {
                    float e = sm.e[b][t];
                    float2 p = *reinterpret_cast<const float2*>(Hrow + (size_t)t * G3_);
                    a0 += e * p.x; a1 += e * p.y;
                }
                float2 o2 = make_float2(a0, a1);
                *reinterpret_cast<float2*>(
                    &g_gpart[(size_t)(8 * 16 + b) * G3_ + colb]) = o2;
                __syncthreads();
            }
        }
        gsync(++bar);
        // ---------------- phase B -------------------------------------------
        for (int task = bid; task < 64; task += NBLK) {
            const int b = task >> 2, kc2 = task & 3;
            const int k = kc2 * 256 + tid;

            float gr = bhh[k], gz = bhh[H_ + k], hn = bhh[2 * H_ + k];
#pragma unroll
            for (int q = 0; q < 8; q++) {
                const float* P = g_gpart + (size_t)(q * 16 + b) * G3_;
                gr += P[k]; gz += P[H_ + k]; hn += P[2 * H_ + k];
            }
            const float* P8 = g_gpart + (size_t)(8 * 16 + b) * G3_;
            gr += P8[k]; gz += P8[H_ + k];
            float inn = P8[2 * H_ + k];

            float r = 1.0f / (1.0f + __expf(-gr));
            float z = 1.0f / (1.0f + __expf(-gz));
            float n = tanhf(inn + r * hn);
            float sold = g_s[b * H_ + k];
            float snew = (1.0f - z) * n + z * sold;
            g_s[b * H_ + k] = snew;
            g_cat[(size_t)(i * B_ + b) * CAT_ + k] = snew;

            sm.pb.s2[tid] = snew;
            __syncthreads();
            const int j = tid & 63, sub = tid >> 6;
            float a = 0.0f;
#pragma unroll 8
            for (int kk = 0; kk < 64; kk++)
                a += sm.pb.s2[sub * 64 + kk] *
                     Ws[(size_t)(kc2 * 256 + sub * 64 + kk) * T_ + j];
            sm.pb.redp[sub][j] = a;
            __syncthreads();
            if (tid < 64)
                g_alignpart[kc2][b][tid] =
                    sm.pb.redp[0][tid] + sm.pb.redp[1][tid] +
                    sm.pb.redp[2][tid] + sm.pb.redp[3][tid];
            __syncthreads();
        }
        gsync(++bar);
    }
}

// ---------------- batched context: c[i,b,:] = e[i,b,:] @ h[b] ---------------
__global__ __launch_bounds__(128)
void ctx_kernel(const float* __restrict__ h)
{
    const int b = blockIdx.x, dc = blockIdx.y, tid = threadIdx.x;
    __shared__ float sh_h[T_][128];
    __shared__ float e_sh[T_];
    const int dbase = dc * 128;
    for (int t = 0; t < T_; t++)
        sh_h[t][tid] = h[(size_t)(b * T_ + t) * D_ + dbase + tid];
    __syncthreads();
    for (int i = 0; i < T_; i++) {
        if (tid < 64) e_sh[tid] = g_E[(i * B_ + b) * T_ + tid];
        __syncthreads();
        float acc = 0.0f;
#pragma unroll 8
        for (int t = 0; t < T_; t++) acc += e_sh[t] * sh_h[t][tid];
        g_cat[(size_t)(i * B_ + b) * CAT_ + H_ + EMB_ + dbase + tid] = acc;
        __syncthreads();
    }
}

// ---------------------------------------------------------------------------
extern "C" void kernel_launch(void* const* d_in, const int* in_sizes, int n_in,
                              void* d_out, int out_size)
{
    (void)in_sizes; (void)n_in; (void)out_size;
    const float* h     = (const float*)d_in[0];
    const float* W_h   = (const float*)d_in[1];
    const float* b_h   = (const float*)d_in[2];
    const float* W_s   = (const float*)d_in[3];
    const float* b_s   = (const float*)d_in[4];
    const float* W_ih  = (const float*)d_in[5];
    const float* b_ih  = (const float*)d_in[6];
    const float* W_hh  = (const float*)d_in[7];
    const float* b_hh  = (const float*)d_in[8];
    const float* W_emb = (const float*)d_in[9];
    const float* b_emb = (const float*)d_in[10];
    const float* W_t   = (const float*)d_in[11];
    const float* b_t   = (const float*)d_in[12];
    const float* W_out = (const float*)d_in[13];
    const float* b_out = (const float*)d_in[14];
    float* out = (float*)d_out;

    float *p_hemb, *p_Hih, *p_cat, *p_tt;
    cudaGetSymbolAddress((void**)&p_hemb, g_hemb);
    cudaGetSymbolAddress((void**)&p_Hih,  g_Hih);
    cudaGetSymbolAddress((void**)&p_cat,  g_cat);
    cudaGetSymbolAddress((void**)&p_tt,   g_tt);

    init_kernel<<<(B_ * H_ + 255) / 256, 256>>>();

    // Precompute: h_emb = h@W_h+b_h (N=64, guarded) ; Hih = h@W_ih+b_ih
    mma_gemm_kernel<false, false><<<dim3(1, (B_ * T_) / 128), 256>>>(
        h, D_, W_h, T_, p_hemb, T_, b_h, D_, T_);
    mma_gemm_kernel<false, false><<<dim3(G3_ / 128, (B_ * T_) / 128), 256>>>(
        h, D_, W_ih, G3_, p_Hih, G3_, b_ih, D_, G3_);

    // Entire 64-step recurrence in ONE persistent cooperative kernel
    recur_kernel<<<NBLK, 256>>>(W_hh, W_s, b_s, b_hh);

    // Batched epilogue
    ctx_kernel<<<dim3(B_, D_ / 128), 128>>>(h);
    mma_gemm_kernel<false, false><<<dim3(EMB_ / 128, (T_ * B_) / 128), 256>>>(
        p_cat, CAT_, W_emb, EMB_, p_cat + H_, CAT_, b_emb, H_, EMB_);
    mma_gemm_kernel<false, false><<<dim3(2 * MO_ / 128, (T_ * B_) / 128), 256>>>(
        p_cat, CAT_, W_t, 2 * MO_, p_tt, 2 * MO_, b_t, CAT_, 2 * MO_);
    // Vocab GEMM with maxout fused into the A-operand load
    mma_gemm_kernel<true, true><<<dim3(V_ / 128, (T_ * B_) / 128), 256>>>(
        p_tt, 2 * MO_, W_out, V_, out, V_, b_out, MO_, V_);
}

// round 7
// speedup vs baseline: 1.0925x; 1.0761x over previous
#include <cuda_runtime.h>
#include <cuda_bf16.h>
#include <math.h>

// Problem constants
#define B_    16
#define T_    64
#define H_    1024
#define D_    2048      // 2H
#define EMB_  512
#define MO_   1024      // maxout units
#define V_    32000
#define G3_   3072      // 3H
#define CAT_  3584      // H + EMB + D
#define NBLK  148       // persistent grid (<= SM count => co-resident)

// Dynamic smem layout for recur_kernel (bytes)
#define WT_ELEMS   (128 * 72)            // one W_hh tile, tf32, padded
#define WHH_OFF    0
#define WHH_BYTES  (3 * WT_ELEMS * 4)    // 110592
#define HSPITCH    1026                  // bank-padded Hih row (floats)
#define HS_OFF     WHH_BYTES
#define HS_BYTES   (21 * HSPITCH * 4 + 24)   // 86208 (rounded)
#define WORK_OFF   (WHH_BYTES + HS_BYTES)    // 196800
#define DSMEM_BYTES (WORK_OFF + 8704 + 4224) // 209728

// ---------------- scratch (device globals) ----------------------------------
__device__ float g_hemb[B_ * T_ * T_];          // h @ W_h + b_h      [b*T+t][j]
__device__ float g_Hih [B_ * T_ * G3_];         // h @ W_ih + b_ih
__device__ float g_s   [B_ * H_];               // GRU state
__device__ float g_E   [T_ * B_ * T_];          // attention weights [i][b][t]
__device__ float g_gpart[9 * B_ * G3_];         // gate partials [q][b][col]
__device__ float g_alignpart[4][B_][T_];        // s@W_s partials [kc2][b][j]
__device__ float g_cat [T_ * B_ * CAT_];        // [s_new | y_emb | c]
__device__ float g_tt  [T_ * B_ * 2 * MO_];     // t_tilde
__device__ unsigned g_barcnt;
__device__ volatile unsigned g_barsense;

// ---------------------------------------------------------------------------
__global__ void init_kernel() {
    int i = blockIdx.x * blockDim.x + threadIdx.x;
    if (i < B_ * H_) g_s[i] = 0.0f;
    if (i < 4 * B_ * T_) ((float*)g_alignpart)[i] = 0.0f;
    if (i == 0) { g_barcnt = 0; g_barsense = 0; }
}

// ---------------- tf32 helpers ----------------------------------------------
__device__ __forceinline__ unsigned f2tf(float f) {
    unsigned r; asm("cvt.rna.tf32.f32 %0, %1;" : "=r"(r) : "f"(f)); return r;
}

// ---------------- tf32 tensor-core GEMM, 128x128x16, double-buffered --------
template <bool PERMUTE, bool AMAX>
__global__ __launch_bounds__(256, 2)
void mma_gemm_kernel(const float* __restrict__ A, int lda,
                     const float* __restrict__ Bm, int ldb,
                     float* __restrict__ C, int ldc,
                     const float* __restrict__ bias, int K, int ncols)
{
    __shared__ unsigned As[2][128][20];   // m-major, pad 20
    __shared__ unsigned Bs[2][16][136];   // k-major, pad 136

    const int tid = threadIdx.x;
    const int wid = tid >> 5, lane = tid & 31;
    const int wm = wid & 3, wn = wid >> 2;          // warps 4(M) x 2(N)
    const int m0 = blockIdx.y * 128, n0 = blockIdx.x * 128;

    const int arow = tid >> 2;                      // 0..63 (+64)
    const int acol = (tid & 3) * 4;
    const int brow = tid >> 5;                      // 0..7 (+8)
    const int bcol = lane * 4;
    int colb = n0 + bcol;
    if (colb > ncols - 4) colb = ncols - 4;         // clamp (ncols mult of 4)

    float acc[2][8][4];
#pragma unroll
    for (int mi = 0; mi < 2; mi++)
#pragma unroll
        for (int ni = 0; ni < 8; ni++)
#pragma unroll
            for (int u = 0; u < 4; u++) acc[mi][ni][u] = 0.0f;

    float4 a0v, a1v, b0v, b1v;

    auto loadA1 = [&](int row, int k0) -> float4 {
        float4 u = *reinterpret_cast<const float4*>(&A[(size_t)row * lda + k0 + acol]);
        if (AMAX) {
            float4 v = *reinterpret_cast<const float4*>(&A[(size_t)row * lda + MO_ + k0 + acol]);
            u.x = fmaxf(u.x, v.x); u.y = fmaxf(u.y, v.y);
            u.z = fmaxf(u.z, v.z); u.w = fmaxf(u.w, v.w);
        }
        return u;
    };
    auto loadT = [&](int k0) {
        a0v = loadA1(m0 + arow, k0);
        a1v = loadA1(m0 + arow + 64, k0);
        b0v = *reinterpret_cast<const float4*>(&Bm[(size_t)(k0 + brow) * ldb + colb]);
        b1v = *reinterpret_cast<const float4*>(&Bm[(size_t)(k0 + brow + 8) * ldb + colb]);
    };
    auto stage = [&](int p) {
        As[p][arow][acol + 0] = f2tf(a0v.x); As[p][arow][acol + 1] = f2tf(a0v.y);
        As[p][arow][acol + 2] = f2tf(a0v.z); As[p][arow][acol + 3] = f2tf(a0v.w);
        As[p][arow + 64][acol + 0] = f2tf(a1v.x); As[p][arow + 64][acol + 1] = f2tf(a1v.y);
        As[p][arow + 64][acol + 2] = f2tf(a1v.z); As[p][arow + 64][acol + 3] = f2tf(a1v.w);
        Bs[p][brow][bcol + 0] = f2tf(b0v.x); Bs[p][brow][bcol + 1] = f2tf(b0v.y);
        Bs[p][brow][bcol + 2] = f2tf(b0v.z); Bs[p][brow][bcol + 3] = f2tf(b0v.w);
        Bs[p][brow + 8][bcol + 0] = f2tf(b1v.x); Bs[p][brow + 8][bcol + 1] = f2tf(b1v.y);
        Bs[p][brow + 8][bcol + 2] = f2tf(b1v.z); Bs[p][brow + 8][bcol + 3] = f2tf(b1v.w);
    };
    auto compute = [&](int p) {
#pragma unroll
        for (int k8 = 0; k8 < 2; k8++) {
            const int kb = k8 * 8;
            unsigned af[2][4], bf[8][2];
#pragma unroll
            for (int mi = 0; mi < 2; mi++) {
                int r = wm * 32 + mi * 16 + (lane >> 2);
                af[mi][0] = As[p][r][kb + (lane & 3)];
                af[mi][1] = As[p][r + 8][kb + (lane & 3)];
                af[mi][2] = As[p][r][kb + (lane & 3) + 4];
                af[mi][3] = As[p][r + 8][kb + (lane & 3) + 4];
            }
#pragma unroll
            for (int ni = 0; ni < 8; ni++) {
                int c = wn * 64 + ni * 8 + (lane >> 2);
                bf[ni][0] = Bs[p][kb + (lane & 3)][c];
                bf[ni][1] = Bs[p][kb + (lane & 3) + 4][c];
            }
#pragma unroll
            for (int mi = 0; mi < 2; mi++)
#pragma unroll
                for (int ni = 0; ni < 8; ni++) {
                    asm volatile(
                        "mma.sync.aligned.m16n8k8.row.col.f32.tf32.tf32.f32 "
                        "{%0,%1,%2,%3}, {%4,%5,%6,%7}, {%8,%9}, {%0,%1,%2,%3};"
                        : "+f"(acc[mi][ni][0]), "+f"(acc[mi][ni][1]),
                          "+f"(acc[mi][ni][2]), "+f"(acc[mi][ni][3])
                        : "r"(af[mi][0]), "r"(af[mi][1]), "r"(af[mi][2]), "r"(af[mi][3]),
                          "r"(bf[ni][0]), "r"(bf[ni][1]));
                }
        }
    };

    loadT(0); stage(0); __syncthreads();
    int buf = 0;
    for (int k0 = 16; k0 < K; k0 += 16) {
        loadT(k0);
        compute(buf);
        stage(buf ^ 1);
        __syncthreads();
        buf ^= 1;
    }
    compute(buf);

#pragma unroll
    for (int mi = 0; mi < 2; mi++) {
        int r = m0 + wm * 32 + mi * 16 + (lane >> 2);
        int r0 = PERMUTE ? ((r & (B_ - 1)) * T_ + (r >> 4)) : r;
        int r8 = r + 8;
        int r1 = PERMUTE ? ((r8 & (B_ - 1)) * T_ + (r8 >> 4)) : r8;
#pragma unroll
        for (int ni = 0; ni < 8; ni++) {
            int c = n0 + wn * 64 + ni * 8 + (lane & 3) * 2;
            if (c < ncols) {
                float bc0 = bias[c], bc1 = bias[c + 1];
                C[(size_t)r0 * ldc + c]     = acc[mi][ni][0] + bc0;
                C[(size_t)r0 * ldc + c + 1] = acc[mi][ni][1] + bc1;
                C[(size_t)r1 * ldc + c]     = acc[mi][ni][2] + bc0;
                C[(size_t)r1 * ldc + c + 1] = acc[mi][ni][3] + bc1;
            }
        }
    }
}

// ---------------- grid-wide sense barrier -----------------------------------
__device__ __forceinline__ void gsync(unsigned target) {
    __syncthreads();
    if (threadIdx.x == 0) {
        __threadfence();
        unsigned old = atomicAdd(&g_barcnt, 1);
        if (old == NBLK - 1) {
            g_barcnt = 0;
            __threadfence();
            g_barsense = target;
        } else {
            while (g_barsense < target) { }
        }
        __threadfence();
    }
    __syncthreads();
}

// ---------------- persistent recurrence kernel (SMEM-resident weights) ------
// Preload: each block owns 2-3 contiguous W_hh tiles (q = id/48 K-slice of
// 128, c = id%48 col-chunk of 64; converted to tf32 once) and ~21 contiguous
// Hih columns (fp32, transposed, bank-padded). The 64-step loop then touches
// L2 only for s, hemb, alignpart and gate partials.
__global__ __launch_bounds__(256, 1)
void recur_kernel(const float* __restrict__ Whh,
                  const float* __restrict__ Ws,
                  const float* __restrict__ bs,
                  const float* __restrict__ bhh)
{
    extern __shared__ unsigned char dsm[];
    unsigned* wt_all = (unsigned*)(dsm + WHH_OFF);
    float*    hs     = (float*)(dsm + HS_OFF);
    unsigned (*sa)[136]  = (unsigned(*)[136])(dsm + WORK_OFF);           // s tile
    float    (*part)[66] = (float(*)[66])(dsm + WORK_OFF + 8704);        // k-reduce
    float    (*e_sh)[65] = (float(*)[65])(dsm + WORK_OFF);               // aliases sa
    float*    s2         = (float*)(dsm + WORK_OFF);                     // phase B
    float    (*redp)[64] = (float(*)[64])(dsm + WORK_OFF + 1024);

    const int tid = threadIdx.x;
    const int bid = blockIdx.x;
    const int lane = tid & 31, wid = tid >> 5;

    // ---- ownership (contiguous ranges) ----
    const int t0 = (384 * bid) / NBLK, t1 = (384 * (bid + 1)) / NBLK;
    const int ntile = t1 - t0;                       // 2 or 3
    const int c0 = (G3_ * bid) / NBLK, c1 = (G3_ * (bid + 1)) / NBLK;
    const int ncols = c1 - c0;                       // 20 or 21

    // ---- preload W_hh tiles (tf32) ----
    for (int j = 0; j < ntile; j++) {
        const int g = t0 + j, q = g / 48, c = g - q * 48;
        const int rr = tid >> 4, c4 = (tid & 15) * 4;
        unsigned* wt = wt_all + j * WT_ELEMS;
#pragma unroll
        for (int p = 0; p < 8; p++) {
            int row = p * 16 + rr;
            float4 v = *reinterpret_cast<const float4*>(
                &Whh[(size_t)(q * 128 + row) * G3_ + c * 64 + c4]);
            wt[row * 72 + c4 + 0] = f2tf(v.x);
            wt[row * 72 + c4 + 1] = f2tf(v.y);
            wt[row * 72 + c4 + 2] = f2tf(v.z);
            wt[row * 72 + c4 + 3] = f2tf(v.w);
        }
    }
    // ---- preload Hih columns (fp32, transposed) ----
    for (int p = tid; p < 1024 * ncols; p += 256) {
        int row = p / ncols, cl = p - row * ncols;
        hs[cl * HSPITCH + row] = g_Hih[(size_t)row * G3_ + c0 + cl];
    }
    __syncthreads();

    unsigned bar = 0;
    for (int i = 0; i < T_; i++) {
        // ---------------- phase A: s@W_hh (mma, smem weights) ----------------
        int qcur = -1;
        for (int j = 0; j < ntile; j++) {
            const int g = t0 + j, q = g / 48, c = g - q * 48;
            if (q != qcur) {
                __syncthreads();
                const int b = tid >> 4, c8 = (tid & 15) * 8;
                const float* src = &g_s[b * H_ + q * 128 + c8];
                float4 v0 = *reinterpret_cast<const float4*>(src);
                float4 v1 = *reinterpret_cast<const float4*>(src + 4);
                sa[b][c8 + 0] = f2tf(v0.x); sa[b][c8 + 1] = f2tf(v0.y);
                sa[b][c8 + 2] = f2tf(v0.z); sa[b][c8 + 3] = f2tf(v0.w);
                sa[b][c8 + 4] = f2tf(v1.x); sa[b][c8 + 5] = f2tf(v1.y);
                sa[b][c8 + 6] = f2tf(v1.z); sa[b][c8 + 7] = f2tf(v1.w);
                qcur = q;
            }
            __syncthreads();
            const int wk = wid >> 2, wn = wid & 3;   // 2 k-halves x 4 n-quarters
            const unsigned* wt = wt_all + j * WT_ELEMS;
            float acc[2][4];
#pragma unroll
            for (int ni = 0; ni < 2; ni++)
#pragma unroll
                for (int u = 0; u < 4; u++) acc[ni][u] = 0.0f;
#pragma unroll
            for (int k8 = 0; k8 < 8; k8++) {
                const int kb = wk * 64 + k8 * 8;
                unsigned af[4];
                af[0] = sa[lane >> 2][kb + (lane & 3)];
                af[1] = sa[(lane >> 2) + 8][kb + (lane & 3)];
                af[2] = sa[lane >> 2][kb + (lane & 3) + 4];
                af[3] = sa[(lane >> 2) + 8][kb + (lane & 3) + 4];
#pragma unroll
                for (int ni = 0; ni < 2; ni++) {
                    const int cc = wn * 16 + ni * 8 + (lane >> 2);
                    unsigned bf0 = wt[(kb + (lane & 3)) * 72 + cc];
                    unsigned bf1 = wt[(kb + (lane & 3) + 4) * 72 + cc];
                    asm volatile(
                        "mma.sync.aligned.m16n8k8.row.col.f32.tf32.tf32.f32 "
                        "{%0,%1,%2,%3}, {%4,%5,%6,%7}, {%8,%9}, {%0,%1,%2,%3};"
                        : "+f"(acc[ni][0]), "+f"(acc[ni][1]),
                          "+f"(acc[ni][2]), "+f"(acc[ni][3])
                        : "r"(af[0]), "r"(af[1]), "r"(af[2]), "r"(af[3]),
                          "r"(bf0), "r"(bf1));
                }
            }
            __syncthreads();
            if (wk == 1) {
#pragma unroll
                for (int ni = 0; ni < 2; ni++) {
                    const int r = lane >> 2, cc = wn * 16 + ni * 8 + (lane & 3) * 2;
                    part[r][cc]         = acc[ni][0];
                    part[r][cc + 1]     = acc[ni][1];
                    part[r + 8][cc]     = acc[ni][2];
                    part[r + 8][cc + 1] = acc[ni][3];
                }
            }
            __syncthreads();
            if (wk == 0) {
#pragma unroll
                for (int ni = 0; ni < 2; ni++) {
                    const int r = lane >> 2, cc = wn * 16 + ni * 8 + (lane & 3) * 2;
                    const int gc = c * 64 + cc;
                    g_gpart[(size_t)(q * 16 + r) * G3_ + gc] =
                        acc[ni][0] + part[r][cc];
                    g_gpart[(size_t)(q * 16 + r) * G3_ + gc + 1] =
                        acc[ni][1] + part[r][cc + 1];
                    g_gpart[(size_t)(q * 16 + r + 8) * G3_ + gc] =
                        acc[ni][2] + part[r + 8][cc];
                    g_gpart[(size_t)(q * 16 + r + 8) * G3_ + gc + 1] =
                        acc[ni][3] + part[r + 8][cc + 1];
                }
            }
        }
        // ---------------- phase A: softmax + e@Hih (smem Hih) ----------------
        __syncthreads();            // sa dead -> e_sh may be written
        {
            const int b2 = (tid >> 5) * 2 + (lane >> 4);
            const int j0 = (lane & 15) * 4;
            float a[4];
#pragma unroll
            for (int u = 0; u < 4; u++) {
                int j = j0 + u;
                float v = bs[j] + g_hemb[(b2 * T_ + i) * T_ + j];
#pragma unroll
                for (int kc = 0; kc < 4; kc++) v += g_alignpart[kc][b2][j];
                a[u] = tanhf(v);
            }
            float m = fmaxf(fmaxf(a[0], a[1]), fmaxf(a[2], a[3]));
#pragma unroll
            for (int o = 8; o > 0; o >>= 1)
                m = fmaxf(m, __shfl_xor_sync(0xffffffffu, m, o));
            float ex[4], ssum = 0.0f;
#pragma unroll
            for (int u = 0; u < 4; u++) { ex[u] = __expf(a[u] - m); ssum += ex[u]; }
#pragma unroll
            for (int o = 8; o > 0; o >>= 1)
                ssum += __shfl_xor_sync(0xffffffffu, ssum, o);
            float inv = 1.0f / ssum;
#pragma unroll
            for (int u = 0; u < 4; u++) {
                e_sh[b2][j0 + u] = ex[u] * inv;
                if (bid == 0) g_E[(i * B_ + b2) * T_ + j0 + u] = ex[u] * inv;
            }
        }
        __syncthreads();
        for (int p = tid; p < 16 * ncols; p += 256) {
            const int b = p / ncols, cl = p - b * ncols;
            const float* hrow = hs + cl * HSPITCH + b * 64;
            float acc = 0.0f;
#pragma unroll
            for (int t = 0; t < 64; t += 2) {
                float2 hv = *reinterpret_cast<const float2*>(hrow + t);
                acc += e_sh[b][t] * hv.x + e_sh[b][t + 1] * hv.y;
            }
            g_gpart[(size_t)(8 * 16 + b) * G3_ + c0 + cl] = acc;
        }
        gsync(++bar);
        // ---------------- phase B: GRU pointwise + s@W_s ---------------------
        if (bid < 64) {
            const int b = bid >> 2, kc2 = bid & 3;
            const int k = kc2 * 256 + tid;

            float gr = bhh[k], gz = bhh[H_ + k], hn = bhh[2 * H_ + k];
#pragma unroll
            for (int q = 0; q < 8; q++) {
                const float* P = g_gpart + (size_t)(q * 16 + b) * G3_;
                gr += P[k]; gz += P[H_ + k]; hn += P[2 * H_ + k];
            }
            const float* P8 = g_gpart + (size_t)(8 * 16 + b) * G3_;
            gr += P8[k]; gz += P8[H_ + k];
            float inn = P8[2 * H_ + k];

            float r = 1.0f / (1.0f + __expf(-gr));
            float z = 1.0f / (1.0f + __expf(-gz));
            float n = tanhf(inn + r * hn);
            float sold = g_s[b * H_ + k];
            float snew = (1.0f - z) * n + z * sold;
            g_s[b * H_ + k] = snew;
            g_cat[(size_t)(i * B_ + b) * CAT_ + k] = snew;

            s2[tid] = snew;
            __syncthreads();
            const int j = tid & 63, sub = tid >> 6;
            float a = 0.0f;
#pragma unroll 8
            for (int kk = 0; kk < 64; kk++)
                a += s2[sub * 64 + kk] *
                     Ws[(size_t)(kc2 * 256 + sub * 64 + kk) * T_ + j];
            redp[sub][j] = a;
            __syncthreads();
            if (tid < 64)
                g_alignpart[kc2][b][tid] =
                    redp[0][tid] + redp[1][tid] + redp[2][tid] + redp[3][tid];
        }
        gsync(++bar);
    }
}

// ---------------- batched context: c[i,b,:] = e[i,b,:] @ h[b] ---------------
__global__ __launch_bounds__(128)
void ctx_kernel(const float* __restrict__ h)
{
    const int b = blockIdx.x, dc = blockIdx.y, tid = threadIdx.x;
    __shared__ float sh_h[T_][128];
    __shared__ float e_sh[T_];
    const int dbase = dc * 128;
    for (int t = 0; t < T_; t++)
        sh_h[t][tid] = h[(size_t)(b * T_ + t) * D_ + dbase + tid];
    __syncthreads();
    for (int i = 0; i < T_; i++) {
        if (tid < 64) e_sh[tid] = g_E[(i * B_ + b) * T_ + tid];
        __syncthreads();
        float acc = 0.0f;
#pragma unroll 8
        for (int t = 0; t < T_; t++) acc += e_sh[t] * sh_h[t][tid];
        g_cat[(size_t)(i * B_ + b) * CAT_ + H_ + EMB_ + dbase + tid] = acc;
        __syncthreads();
    }
}

// ---------------------------------------------------------------------------
extern "C" void kernel_launch(void* const* d_in, const int* in_sizes, int n_in,
                              void* d_out, int out_size)
{
    (void)in_sizes; (void)n_in; (void)out_size;
    const float* h     = (const float*)d_in[0];
    const float* W_h   = (const float*)d_in[1];
    const float* b_h   = (const float*)d_in[2];
    const float* W_s   = (const float*)d_in[3];
    const float* b_s   = (const float*)d_in[4];
    const float* W_ih  = (const float*)d_in[5];
    const float* b_ih  = (const float*)d_in[6];
    const float* W_hh  = (const float*)d_in[7];
    const float* b_hh  = (const float*)d_in[8];
    const float* W_emb = (const float*)d_in[9];
    const float* b_emb = (const float*)d_in[10];
    const float* W_t   = (const float*)d_in[11];
    const float* b_t   = (const float*)d_in[12];
    const float* W_out = (const float*)d_in[13];
    const float* b_out = (const float*)d_in[14];
    float* out = (float*)d_out;

    float *p_hemb, *p_Hih, *p_cat, *p_tt;
    cudaGetSymbolAddress((void**)&p_hemb, g_hemb);
    cudaGetSymbolAddress((void**)&p_Hih,  g_Hih);
    cudaGetSymbolAddress((void**)&p_cat,  g_cat);
    cudaGetSymbolAddress((void**)&p_tt,   g_tt);

    static int smem_set = 0;
    if (!smem_set) {
        cudaFuncSetAttribute(recur_kernel,
                             cudaFuncAttributeMaxDynamicSharedMemorySize,
                             DSMEM_BYTES);
        smem_set = 1;
    }

    init_kernel<<<(B_ * H_ + 255) / 256, 256>>>();

    // Precompute: h_emb = h@W_h+b_h (N=64, guarded) ; Hih = h@W_ih+b_ih
    mma_gemm_kernel<false, false><<<dim3(1, (B_ * T_) / 128), 256>>>(
        h, D_, W_h, T_, p_hemb, T_, b_h, D_, T_);
    mma_gemm_kernel<false, false><<<dim3(G3_ / 128, (B_ * T_) / 128), 256>>>(
        h, D_, W_ih, G3_, p_Hih, G3_, b_ih, D_, G3_);

    // Entire 64-step recurrence in ONE persistent cooperative kernel
    recur_kernel<<<NBLK, 256, DSMEM_BYTES>>>(W_hh, W_s, b_s, b_hh);

    // Batched epilogue
    ctx_kernel<<<dim3(B_, D_ / 128), 128>>>(h);
    mma_gemm_kernel<false, false><<<dim3(EMB_ / 128, (T_ * B_) / 128), 256>>>(
        p_cat, CAT_, W_emb, EMB_, p_cat + H_, CAT_, b_emb, H_, EMB_);
    mma_gemm_kernel<false, false><<<dim3(2 * MO_ / 128, (T_ * B_) / 128), 256>>>(
        p_cat, CAT_, W_t, 2 * MO_, p_tt, 2 * MO_, b_t, CAT_, 2 * MO_);
    // Vocab GEMM with maxout fused into the A-operand load
    mma_gemm_kernel<true, true><<<dim3(V_ / 128, (T_ * B_) / 128), 256>>>(
        p_tt, 2 * MO_, W_out, V_, out, V_, b_out, MO_, V_);
}

// round 8
// speedup vs baseline: 1.0964x; 1.0036x over previous
#include <cuda_runtime.h>
#include <cuda_bf16.h>
#include <math.h>

// Problem constants
#define B_    16
#define T_    64
#define H_    1024
#define D_    2048      // 2H
#define EMB_  512
#define MO_   1024      // maxout units
#define V_    32000
#define G3_   3072      // 3H
#define CAT_  3584      // H + EMB + D
#define NBLK  148       // persistent grid (<= SM count => co-resident)

// Dynamic smem layout for recur_kernel (bytes)
#define WT_ELEMS   (128 * 72)            // one W_hh tile, tf32, padded
#define WHH_BYTES  (3 * WT_ELEMS * 4)    // 110592
#define HSPITCH    1026                  // bank-padded Hih row (floats)
#define HS_OFF     WHH_BYTES
#define HS_BYTES   (21 * HSPITCH * 4 + 24)   // 86208
#define SA_OFF     (WHH_BYTES + HS_BYTES)    // 196800  (s tile / phase-B scratch)
#define PART_OFF   (SA_OFF + 8704)           // 205504  (2 x 16 x 66 reduce)
#define E_OFF      (PART_OFF + 8448)         // 213952  (e weights)
#define DSMEM_BYTES (E_OFF + 4160)           // 218112

// ---------------- scratch (device globals) ----------------------------------
__device__ float g_hemb[B_ * T_ * T_];          // h @ W_h + b_h      [b*T+t][j]
__device__ float g_Hih [B_ * T_ * G3_];         // h @ W_ih + b_ih
__device__ float g_s   [B_ * H_];               // GRU state
__device__ float g_E   [T_ * B_ * T_];          // attention weights [i][b][t]
__device__ float g_gpart[9 * B_ * G3_];         // gate partials [q][b][col]
__device__ float g_alignpart[2][B_][T_];        // s@W_s partials [half][b][j]
__device__ float g_cat [T_ * B_ * CAT_];        // [s_new | y_emb | c]
__device__ float g_tt  [T_ * B_ * 2 * MO_];     // t_tilde
__device__ unsigned g_barcnt;
__device__ volatile unsigned g_barsense;

// ---------------------------------------------------------------------------
__global__ void init_kernel() {
    int i = blockIdx.x * blockDim.x + threadIdx.x;
    if (i < B_ * H_) g_s[i] = 0.0f;
    if (i < 2 * B_ * T_) ((float*)g_alignpart)[i] = 0.0f;
    if (i == 0) { g_barcnt = 0; g_barsense = 0; }
}

// ---------------- tf32 helpers ----------------------------------------------
__device__ __forceinline__ unsigned f2tf(float f) {
    unsigned r; asm("cvt.rna.tf32.f32 %0, %1;" : "=r"(r) : "f"(f)); return r;
}

// ---------------- tf32 tensor-core GEMM, 128x128x16, double-buffered --------
template <bool PERMUTE, bool AMAX>
__global__ __launch_bounds__(256, 2)
void mma_gemm_kernel(const float* __restrict__ A, int lda,
                     const float* __restrict__ Bm, int ldb,
                     float* __restrict__ C, int ldc,
                     const float* __restrict__ bias, int K, int ncols)
{
    __shared__ unsigned As[2][128][20];   // m-major, pad 20
    __shared__ unsigned Bs[2][16][136];   // k-major, pad 136

    const int tid = threadIdx.x;
    const int wid = tid >> 5, lane = tid & 31;
    const int wm = wid & 3, wn = wid >> 2;          // warps 4(M) x 2(N)
    const int m0 = blockIdx.y * 128, n0 = blockIdx.x * 128;

    const int arow = tid >> 2;                      // 0..63 (+64)
    const int acol = (tid & 3) * 4;
    const int brow = tid >> 5;                      // 0..7 (+8)
    const int bcol = lane * 4;
    int colb = n0 + bcol;
    if (colb > ncols - 4) colb = ncols - 4;         // clamp (ncols mult of 4)

    float acc[2][8][4];
#pragma unroll
    for (int mi = 0; mi < 2; mi++)
#pragma unroll
        for (int ni = 0; ni < 8; ni++)
#pragma unroll
            for (int u = 0; u < 4; u++) acc[mi][ni][u] = 0.0f;

    float4 a0v, a1v, b0v, b1v;

    auto loadA1 = [&](int row, int k0) -> float4 {
        float4 u = *reinterpret_cast<const float4*>(&A[(size_t)row * lda + k0 + acol]);
        if (AMAX) {
            float4 v = *reinterpret_cast<const float4*>(&A[(size_t)row * lda + MO_ + k0 + acol]);
            u.x = fmaxf(u.x, v.x); u.y = fmaxf(u.y, v.y);
            u.z = fmaxf(u.z, v.z); u.w = fmaxf(u.w, v.w);
        }
        return u;
    };
    auto loadT = [&](int k0) {
        a0v = loadA1(m0 + arow, k0);
        a1v = loadA1(m0 + arow + 64, k0);
        b0v = *reinterpret_cast<const float4*>(&Bm[(size_t)(k0 + brow) * ldb + colb]);
        b1v = *reinterpret_cast<const float4*>(&Bm[(size_t)(k0 + brow + 8) * ldb + colb]);
    };
    auto stage = [&](int p) {
        As[p][arow][acol + 0] = f2tf(a0v.x); As[p][arow][acol + 1] = f2tf(a0v.y);
        As[p][arow][acol + 2] = f2tf(a0v.z); As[p][arow][acol + 3] = f2tf(a0v.w);
        As[p][arow + 64][acol + 0] = f2tf(a1v.x); As[p][arow + 64][acol + 1] = f2tf(a1v.y);
        As[p][arow + 64][acol + 2] = f2tf(a1v.z); As[p][arow + 64][acol + 3] = f2tf(a1v.w);
        Bs[p][brow][bcol + 0] = f2tf(b0v.x); Bs[p][brow][bcol + 1] = f2tf(b0v.y);
        Bs[p][brow][bcol + 2] = f2tf(b0v.z); Bs[p][brow][bcol + 3] = f2tf(b0v.w);
        Bs[p][brow + 8][bcol + 0] = f2tf(b1v.x); Bs[p][brow + 8][bcol + 1] = f2tf(b1v.y);
        Bs[p][brow + 8][bcol + 2] = f2tf(b1v.z); Bs[p][brow + 8][bcol + 3] = f2tf(b1v.w);
    };
    auto compute = [&](int p) {
#pragma unroll
        for (int k8 = 0; k8 < 2; k8++) {
            const int kb = k8 * 8;
            unsigned af[2][4], bf[8][2];
#pragma unroll
            for (int mi = 0; mi < 2; mi++) {
                int r = wm * 32 + mi * 16 + (lane >> 2);
                af[mi][0] = As[p][r][kb + (lane & 3)];
                af[mi][1] = As[p][r + 8][kb + (lane & 3)];
                af[mi][2] = As[p][r][kb + (lane & 3) + 4];
                af[mi][3] = As[p][r + 8][kb + (lane & 3) + 4];
            }
#pragma unroll
            for (int ni = 0; ni < 8; ni++) {
                int c = wn * 64 + ni * 8 + (lane >> 2);
                bf[ni][0] = Bs[p][kb + (lane & 3)][c];
                bf[ni][1] = Bs[p][kb + (lane & 3) + 4][c];
            }
#pragma unroll
            for (int mi = 0; mi < 2; mi++)
#pragma unroll
                for (int ni = 0; ni < 8; ni++) {
                    asm volatile(
                        "mma.sync.aligned.m16n8k8.row.col.f32.tf32.tf32.f32 "
                        "{%0,%1,%2,%3}, {%4,%5,%6,%7}, {%8,%9}, {%0,%1,%2,%3};"
                        : "+f"(acc[mi][ni][0]), "+f"(acc[mi][ni][1]),
                          "+f"(acc[mi][ni][2]), "+f"(acc[mi][ni][3])
                        : "r"(af[mi][0]), "r"(af[mi][1]), "r"(af[mi][2]), "r"(af[mi][3]),
                          "r"(bf[ni][0]), "r"(bf[ni][1]));
                }
        }
    };

    loadT(0); stage(0); __syncthreads();
    int buf = 0;
    for (int k0 = 16; k0 < K; k0 += 16) {
        loadT(k0);
        compute(buf);
        stage(buf ^ 1);
        __syncthreads();
        buf ^= 1;
    }
    compute(buf);

#pragma unroll
    for (int mi = 0; mi < 2; mi++) {
        int r = m0 + wm * 32 + mi * 16 + (lane >> 2);
        int r0 = PERMUTE ? ((r & (B_ - 1)) * T_ + (r >> 4)) : r;
        int r8 = r + 8;
        int r1 = PERMUTE ? ((r8 & (B_ - 1)) * T_ + (r8 >> 4)) : r8;
#pragma unroll
        for (int ni = 0; ni < 8; ni++) {
            int c = n0 + wn * 64 + ni * 8 + (lane & 3) * 2;
            if (c < ncols) {
                float bc0 = bias[c], bc1 = bias[c + 1];
                C[(size_t)r0 * ldc + c]     = acc[mi][ni][0] + bc0;
                C[(size_t)r0 * ldc + c + 1] = acc[mi][ni][1] + bc1;
                C[(size_t)r1 * ldc + c]     = acc[mi][ni][2] + bc0;
                C[(size_t)r1 * ldc + c + 1] = acc[mi][ni][3] + bc1;
            }
        }
    }
}

// ---------------- grid-wide sense barrier -----------------------------------
__device__ __forceinline__ void gsync(unsigned target) {
    __syncthreads();
    if (threadIdx.x == 0) {
        __threadfence();
        unsigned old = atomicAdd(&g_barcnt, 1);
        if (old == NBLK - 1) {
            g_barcnt = 0;
            __threadfence();
            g_barsense = target;
        } else {
            while (g_barsense < target) { __nanosleep(32); }
        }
        __threadfence();
    }
    __syncthreads();
}

// ---------------- persistent recurrence kernel (512 thr, 16 warps/SM) -------
// Tile map: q = bid%8 (all of a block's tiles share one q K-slice);
//           col-groups per q: 19 (q<4) or 18 (q>=4); each block owns 2-3
//           contiguous 64-col W_hh tiles (tf32, smem) + ~21 Hih cols (fp32).
// Phase A: two tiles computed concurrently by two 8-warp halves; then
//          softmax + e@Hih. Phase B: 32 blocks, 512 k each: GRU pointwise +
//          s@W_s partials (2 halves).
__global__ __launch_bounds__(512, 1)
void recur_kernel(const float* __restrict__ Whh,
                  const float* __restrict__ Ws,
                  const float* __restrict__ bs,
                  const float* __restrict__ bhh)
{
    extern __shared__ unsigned char dsm[];
    unsigned* wt_all = (unsigned*)dsm;
    float*    hs     = (float*)(dsm + HS_OFF);
    unsigned (*sa)[136]     = (unsigned(*)[136])(dsm + SA_OFF);
    float    (*part)[16][66] = (float(*)[16][66])(dsm + PART_OFF);
    float    (*e_sh)[65]    = (float(*)[65])(dsm + E_OFF);
    float*    s2            = (float*)(dsm + SA_OFF);          // phase B alias
    float    (*redp)[64]    = (float(*)[64])(dsm + SA_OFF + 2048);

    const int tid = threadIdx.x;
    const int bid = blockIdx.x;
    const int lane = tid & 31, wid = tid >> 5;

    // ---- W_hh tile ownership: same q for all of this block's tiles ----
    const int q = bid & 7;
    const int gidx = bid >> 3;
    const int gcount = (q < 4) ? 19 : 18;
    const int c0t = gidx * 48 / gcount;
    const int c1t = (gidx + 1) * 48 / gcount;
    const int ntile = c1t - c0t;                     // 2 or 3

    // ---- Hih column ownership (independent contiguous map) ----
    const int c0h = (G3_ * bid) / NBLK, c1h = (G3_ * (bid + 1)) / NBLK;
    const int ncolsh = c1h - c0h;                    // 20 or 21

    // ---- preload W_hh tiles (tf32) ----
    for (int j = 0; j < ntile; j++) {
        const int c = c0t + j;
        const int rr = tid >> 4, c4 = (tid & 15) * 4;   // rr 0..31
        unsigned* wt = wt_all + j * WT_ELEMS;
#pragma unroll
        for (int p = 0; p < 4; p++) {
            int row = p * 32 + rr;
            float4 v = *reinterpret_cast<const float4*>(
                &Whh[(size_t)(q * 128 + row) * G3_ + c * 64 + c4]);
            wt[row * 72 + c4 + 0] = f2tf(v.x);
            wt[row * 72 + c4 + 1] = f2tf(v.y);
            wt[row * 72 + c4 + 2] = f2tf(v.z);
            wt[row * 72 + c4 + 3] = f2tf(v.w);
        }
    }
    // ---- preload Hih columns (fp32, transposed) ----
    for (int p = tid; p < 1024 * ncolsh; p += 512) {
        int row = p / ncolsh, cl = p - row * ncolsh;
        hs[cl * HSPITCH + row] = g_Hih[(size_t)row * G3_ + c0h + cl];
    }
    __syncthreads();

    const int half = wid >> 3;          // 0/1: which concurrent tile
    const int hwid = wid & 7;           // warp within the 8-warp half
    const int wk = hwid >> 2, wn = hwid & 3;

    unsigned bar = 0;
    for (int i = 0; i < T_; i++) {
        // ---- phase A: stage s (q slice) once ----
        {
            const int b = tid >> 5, c4 = (tid & 31) * 4;
            float4 v = *reinterpret_cast<const float4*>(&g_s[b * H_ + q * 128 + c4]);
            sa[b][c4 + 0] = f2tf(v.x); sa[b][c4 + 1] = f2tf(v.y);
            sa[b][c4 + 2] = f2tf(v.z); sa[b][c4 + 3] = f2tf(v.w);
        }
        __syncthreads();
        // ---- phase A: s@W_hh, two tiles at a time ----
        for (int jj = 0; jj < ntile; jj += 2) {
            const int nt = (ntile - jj < 2) ? (ntile - jj) : 2;
            const int j = jj + half;
            float acc[2][4];
#pragma unroll
            for (int ni = 0; ni < 2; ni++)
#pragma unroll
                for (int u = 0; u < 4; u++) acc[ni][u] = 0.0f;
            if (half < nt) {
                const unsigned* wt = wt_all + j * WT_ELEMS;
#pragma unroll
                for (int k8 = 0; k8 < 8; k8++) {
                    const int kb = wk * 64 + k8 * 8;
                    unsigned af[4];
                    af[0] = sa[lane >> 2][kb + (lane & 3)];
                    af[1] = sa[(lane >> 2) + 8][kb + (lane & 3)];
                    af[2] = sa[lane >> 2][kb + (lane & 3) + 4];
                    af[3] = sa[(lane >> 2) + 8][kb + (lane & 3) + 4];
#pragma unroll
                    for (int ni = 0; ni < 2; ni++) {
                        const int cc = wn * 16 + ni * 8 + (lane >> 2);
                        unsigned bf0 = wt[(kb + (lane & 3)) * 72 + cc];
                        unsigned bf1 = wt[(kb + (lane & 3) + 4) * 72 + cc];
                        asm volatile(
                            "mma.sync.aligned.m16n8k8.row.col.f32.tf32.tf32.f32 "
                            "{%0,%1,%2,%3}, {%4,%5,%6,%7}, {%8,%9}, {%0,%1,%2,%3};"
                            : "+f"(acc[ni][0]), "+f"(acc[ni][1]),
                              "+f"(acc[ni][2]), "+f"(acc[ni][3])
                            : "r"(af[0]), "r"(af[1]), "r"(af[2]), "r"(af[3]),
                              "r"(bf0), "r"(bf1));
                    }
                }
            }
            __syncthreads();
            if (half < nt && wk == 1) {
#pragma unroll
                for (int ni = 0; ni < 2; ni++) {
                    const int r = lane >> 2, cc = wn * 16 + ni * 8 + (lane & 3) * 2;
                    part[half][r][cc]         = acc[ni][0];
                    part[half][r][cc + 1]     = acc[ni][1];
                    part[half][r + 8][cc]     = acc[ni][2];
                    part[half][r + 8][cc + 1] = acc[ni][3];
                }
            }
            __syncthreads();
            if (half < nt && wk == 0) {
                const int c = c0t + j;
#pragma unroll
                for (int ni = 0; ni < 2; ni++) {
                    const int r = lane >> 2, cc = wn * 16 + ni * 8 + (lane & 3) * 2;
                    const int gc = c * 64 + cc;
                    g_gpart[(size_t)(q * 16 + r) * G3_ + gc] =
                        acc[ni][0] + part[half][r][cc];
                    g_gpart[(size_t)(q * 16 + r) * G3_ + gc + 1] =
                        acc[ni][1] + part[half][r][cc + 1];
                    g_gpart[(size_t)(q * 16 + r + 8) * G3_ + gc] =
                        acc[ni][2] + part[half][r + 8][cc];
                    g_gpart[(size_t)(q * 16 + r + 8) * G3_ + gc + 1] =
                        acc[ni][3] + part[half][r + 8][cc + 1];
                }
            }
            __syncthreads();
        }
        // ---- phase A: softmax (first 256 threads; identical arithmetic) ----
        if (tid < 256) {
            const int b2 = (tid >> 5) * 2 + (lane >> 4);
            const int j0 = (lane & 15) * 4;
            float a[4];
#pragma unroll
            for (int u = 0; u < 4; u++) {
                int jx = j0 + u;
                float v = bs[jx] + g_hemb[(b2 * T_ + i) * T_ + jx];
#pragma unroll
                for (int kc = 0; kc < 2; kc++) v += g_alignpart[kc][b2][jx];
                a[u] = tanhf(v);
            }
            float m = fmaxf(fmaxf(a[0], a[1]), fmaxf(a[2], a[3]));
#pragma unroll
            for (int o = 8; o > 0; o >>= 1)
                m = fmaxf(m, __shfl_xor_sync(0xffffffffu, m, o));
            float ex[4], ssum = 0.0f;
#pragma unroll
            for (int u = 0; u < 4; u++) { ex[u] = __expf(a[u] - m); ssum += ex[u]; }
#pragma unroll
            for (int o = 8; o > 0; o >>= 1)
                ssum += __shfl_xor_sync(0xffffffffu, ssum, o);
            float inv = 1.0f / ssum;
#pragma unroll
            for (int u = 0; u < 4; u++) {
                e_sh[b2][j0 + u] = ex[u] * inv;
                if (bid == 0) g_E[(i * B_ + b2) * T_ + j0 + u] = ex[u] * inv;
            }
        }
        __syncthreads();
        // ---- phase A: gi = e @ Hih (smem Hih) ----
        for (int p = tid; p < 16 * ncolsh; p += 512) {
            const int b = p / ncolsh, cl = p - b * ncolsh;
            const float* hrow = hs + cl * HSPITCH + b * 64;
            float a0 = 0.0f, a1 = 0.0f;
#pragma unroll
            for (int t = 0; t < 64; t += 4) {
                float2 h0 = *reinterpret_cast<const float2*>(hrow + t);
                float2 h1 = *reinterpret_cast<const float2*>(hrow + t + 2);
                a0 += e_sh[b][t] * h0.x + e_sh[b][t + 1] * h0.y;
                a1 += e_sh[b][t + 2] * h1.x + e_sh[b][t + 3] * h1.y;
            }
            g_gpart[(size_t)(8 * 16 + b) * G3_ + c0h + cl] = a0 + a1;
        }
        gsync(++bar);
        // ---- phase B: GRU pointwise + s@W_s (32 blocks x 512 k) ----
        if (bid < 32) {
            const int b = bid >> 1, hf = bid & 1;
            const int k = hf * 512 + tid;

            float gr = bhh[k], gz = bhh[H_ + k], hn = bhh[2 * H_ + k];
#pragma unroll
            for (int qq = 0; qq < 8; qq++) {
                const float* P = g_gpart + (size_t)(qq * 16 + b) * G3_;
                gr += P[k]; gz += P[H_ + k]; hn += P[2 * H_ + k];
            }
            const float* P8 = g_gpart + (size_t)(8 * 16 + b) * G3_;
            gr += P8[k]; gz += P8[H_ + k];
            float inn = P8[2 * H_ + k];

            float r = 1.0f / (1.0f + __expf(-gr));
            float z = 1.0f / (1.0f + __expf(-gz));
            float n = tanhf(inn + r * hn);
            float sold = g_s[b * H_ + k];
            float snew = (1.0f - z) * n + z * sold;
            g_s[b * H_ + k] = snew;
            g_cat[(size_t)(i * B_ + b) * CAT_ + k] = snew;

            s2[tid] = snew;
            __syncthreads();
            const int j = tid & 63, sub = tid >> 6;     // 8 subs x 64 j
            float a = 0.0f;
#pragma unroll 8
            for (int kk = 0; kk < 64; kk++)
                a += s2[sub * 64 + kk] *
                     Ws[(size_t)(hf * 512 + sub * 64 + kk) * T_ + j];
            redp[sub][j] = a;
            __syncthreads();
            if (tid < 64)
                g_alignpart[hf][b][tid] =
                    redp[0][tid] + redp[1][tid] + redp[2][tid] + redp[3][tid] +
                    redp[4][tid] + redp[5][tid] + redp[6][tid] + redp[7][tid];
        }
        gsync(++bar);
    }
}

// ---------------- batched context: c[i,b,:] = e[i,b,:] @ h[b] ---------------
__global__ __launch_bounds__(128)
void ctx_kernel(const float* __restrict__ h)
{
    const int b = blockIdx.x, dc = blockIdx.y, tid = threadIdx.x;
    __shared__ float sh_h[T_][128];
    __shared__ float e_sh[T_];
    const int dbase = dc * 128;
    for (int t = 0; t < T_; t++)
        sh_h[t][tid] = h[(size_t)(b * T_ + t) * D_ + dbase + tid];
    __syncthreads();
    for (int i = 0; i < T_; i++) {
        if (tid < 64) e_sh[tid] = g_E[(i * B_ + b) * T_ + tid];
        __syncthreads();
        float acc = 0.0f;
#pragma unroll 8
        for (int t = 0; t < T_; t++) acc += e_sh[t] * sh_h[t][tid];
        g_cat[(size_t)(i * B_ + b) * CAT_ + H_ + EMB_ + dbase + tid] = acc;
        __syncthreads();
    }
}

// ---------------------------------------------------------------------------
extern "C" void kernel_launch(void* const* d_in, const int* in_sizes, int n_in,
                              void* d_out, int out_size)
{
    (void)in_sizes; (void)n_in; (void)out_size;
    const float* h     = (const float*)d_in[0];
    const float* W_h   = (const float*)d_in[1];
    const float* b_h   = (const float*)d_in[2];
    const float* W_s   = (const float*)d_in[3];
    const float* b_s   = (const float*)d_in[4];
    const float* W_ih  = (const float*)d_in[5];
    const float* b_ih  = (const float*)d_in[6];
    const float* W_hh  = (const float*)d_in[7];
    const float* b_hh  = (const float*)d_in[8];
    const float* W_emb = (const float*)d_in[9];
    const float* b_emb = (const float*)d_in[10];
    const float* W_t   = (const float*)d_in[11];
    const float* b_t   = (const float*)d_in[12];
    const float* W_out = (const float*)d_in[13];
    const float* b_out = (const float*)d_in[14];
    float* out = (float*)d_out;

    float *p_hemb, *p_Hih, *p_cat, *p_tt;
    cudaGetSymbolAddress((void**)&p_hemb, g_hemb);
    cudaGetSymbolAddress((void**)&p_Hih,  g_Hih);
    cudaGetSymbolAddress((void**)&p_cat,  g_cat);
    cudaGetSymbolAddress((void**)&p_tt,   g_tt);

    static int smem_set = 0;
    if (!smem_set) {
        cudaFuncSetAttribute(recur_kernel,
                             cudaFuncAttributeMaxDynamicSharedMemorySize,
                             DSMEM_BYTES);
        smem_set = 1;
    }

    init_kernel<<<(B_ * H_ + 255) / 256, 256>>>();

    // Precompute: h_emb = h@W_h+b_h (N=64, guarded) ; Hih = h@W_ih+b_ih
    mma_gemm_kernel<false, false><<<dim3(1, (B_ * T_) / 128), 256>>>(
        h, D_, W_h, T_, p_hemb, T_, b_h, D_, T_);
    mma_gemm_kernel<false, false><<<dim3(G3_ / 128, (B_ * T_) / 128), 256>>>(
        h, D_, W_ih, G3_, p_Hih, G3_, b_ih, D_, G3_);

    // Entire 64-step recurrence in ONE persistent cooperative kernel
    recur_kernel<<<NBLK, 512, DSMEM_BYTES>>>(W_hh, W_s, b_s, b_hh);

    // Batched epilogue
    ctx_kernel<<<dim3(B_, D_ / 128), 128>>>(h);
    mma_gemm_kernel<false, false><<<dim3(EMB_ / 128, (T_ * B_) / 128), 256>>>(
        p_cat, CAT_, W_emb, EMB_, p_cat + H_, CAT_, b_emb, H_, EMB_);
    mma_gemm_kernel<false, false><<<dim3(2 * MO_ / 128, (T_ * B_) / 128), 256>>>(
        p_cat, CAT_, W_t, 2 * MO_, p_tt, 2 * MO_, b_t, CAT_, 2 * MO_);
    // Vocab GEMM with maxout fused into the A-operand load
    mma_gemm_kernel<true, true><<<dim3(V_ / 128, (T_ * B_) / 128), 256>>>(
        p_tt, 2 * MO_, W_out, V_, out, V_, b_out, MO_, V_);
}

// round 9
// speedup vs baseline: 1.1289x; 1.0296x over previous
#include <cuda_runtime.h>
#include <cuda_bf16.h>
#include <math.h>

// Problem constants
#define B_    16
#define T_    64
#define H_    1024
#define D_    2048      // 2H
#define EMB_  512
#define MO_   1024      // maxout units
#define V_    32000
#define G3_   3072      // 3H
#define CAT_  3584      // H + EMB + D
#define NBLK  148       // persistent grid (<= SM count => co-resident)

// Dynamic smem layout for recur_kernel (bytes)
#define WT_ELEMS   (128 * 72)            // one W_hh tile, tf32, padded
#define WHH_BYTES  (3 * WT_ELEMS * 4)    // 110592
#define HSPITCH    1026                  // bank-padded Hih row (floats)
#define HS_OFF     WHH_BYTES
#define HS_BYTES   (21 * HSPITCH * 4 + 24)   // 86208
#define SA_OFF     (WHH_BYTES + HS_BYTES)    // 196800  (s tile / phase-B scratch)
#define PART_OFF   (SA_OFF + 8704)           // 205504  (2 x 16 x 66 reduce)
#define E_OFF      (PART_OFF + 8448)         // 213952  (e weights)
#define DSMEM_BYTES (E_OFF + 4160)           // 218112

// Dynamic smem for the 256x128 GEMM (bytes)
#define G2_AS_BYTES (2 * 256 * 20 * 4)       // 40960
#define G2_BS_BYTES (2 * 16 * 136 * 4)       // 17408
#define G2_SMEM     (G2_AS_BYTES + G2_BS_BYTES)  // 58368

// ---------------- scratch (device globals) ----------------------------------
__device__ float g_hemb[B_ * T_ * T_];          // h @ W_h + b_h      [b*T+t][j]
__device__ float g_Hih [B_ * T_ * G3_];         // h @ W_ih + b_ih
__device__ float g_s   [B_ * H_];               // GRU state
__device__ float g_E   [T_ * B_ * T_];          // attention weights [i][b][t]
__device__ float g_gpart[9 * B_ * G3_];         // gate partials [q][b][col]
__device__ float g_alignpart[2][B_][T_];        // s@W_s partials [half][b][j]
__device__ float g_cat [T_ * B_ * CAT_];        // [s_new | y_emb | c]
__device__ float g_tt  [T_ * B_ * 2 * MO_];     // t_tilde
__device__ float g_tmax[T_ * B_ * MO_];         // maxout result
__device__ volatile int g_arrive[NBLK];         // per-block arrival flags
__device__ volatile unsigned g_barsense;        // release word

// ---------------------------------------------------------------------------
__global__ void init_kernel() {
    int i = blockIdx.x * blockDim.x + threadIdx.x;
    if (i < B_ * H_) g_s[i] = 0.0f;
    if (i < 2 * B_ * T_) ((float*)g_alignpart)[i] = 0.0f;
    if (i < NBLK) g_arrive[i] = 0;
    if (i == 0) g_barsense = 0;
}

// ---------------- tf32 helpers ----------------------------------------------
__device__ __forceinline__ unsigned f2tf(float f) {
    unsigned r; asm("cvt.rna.tf32.f32 %0, %1;" : "=r"(r) : "f"(f)); return r;
}

// ---------------- tf32 tensor-core GEMM, 128x128x16, double-buffered --------
template <bool PERMUTE>
__global__ __launch_bounds__(256, 2)
void mma_gemm_kernel(const float* __restrict__ A, int lda,
                     const float* __restrict__ Bm, int ldb,
                     float* __restrict__ C, int ldc,
                     const float* __restrict__ bias, int K, int ncols)
{
    __shared__ unsigned As[2][128][20];   // m-major, pad 20
    __shared__ unsigned Bs[2][16][136];   // k-major, pad 136

    const int tid = threadIdx.x;
    const int wid = tid >> 5, lane = tid & 31;
    const int wm = wid & 3, wn = wid >> 2;          // warps 4(M) x 2(N)
    const int m0 = blockIdx.y * 128, n0 = blockIdx.x * 128;

    const int arow = tid >> 2;                      // 0..63 (+64)
    const int acol = (tid & 3) * 4;
    const int brow = tid >> 5;                      // 0..7 (+8)
    const int bcol = lane * 4;
    int colb = n0 + bcol;
    if (colb > ncols - 4) colb = ncols - 4;         // clamp (ncols mult of 4)

    float acc[2][8][4];
#pragma unroll
    for (int mi = 0; mi < 2; mi++)
#pragma unroll
        for (int ni = 0; ni < 8; ni++)
#pragma unroll
            for (int u = 0; u < 4; u++) acc[mi][ni][u] = 0.0f;

    float4 a0v, a1v, b0v, b1v;

    auto loadT = [&](int k0) {
        a0v = *reinterpret_cast<const float4*>(&A[(size_t)(m0 + arow) * lda + k0 + acol]);
        a1v = *reinterpret_cast<const float4*>(&A[(size_t)(m0 + arow + 64) * lda + k0 + acol]);
        b0v = *reinterpret_cast<const float4*>(&Bm[(size_t)(k0 + brow) * ldb + colb]);
        b1v = *reinterpret_cast<const float4*>(&Bm[(size_t)(k0 + brow + 8) * ldb + colb]);
    };
    auto stage = [&](int p) {
        As[p][arow][acol + 0] = f2tf(a0v.x); As[p][arow][acol + 1] = f2tf(a0v.y);
        As[p][arow][acol + 2] = f2tf(a0v.z); As[p][arow][acol + 3] = f2tf(a0v.w);
        As[p][arow + 64][acol + 0] = f2tf(a1v.x); As[p][arow + 64][acol + 1] = f2tf(a1v.y);
        As[p][arow + 64][acol + 2] = f2tf(a1v.z); As[p][arow + 64][acol + 3] = f2tf(a1v.w);
        Bs[p][brow][bcol + 0] = f2tf(b0v.x); Bs[p][brow][bcol + 1] = f2tf(b0v.y);
        Bs[p][brow][bcol + 2] = f2tf(b0v.z); Bs[p][brow][bcol + 3] = f2tf(b0v.w);
        Bs[p][brow + 8][bcol + 0] = f2tf(b1v.x); Bs[p][brow + 8][bcol + 1] = f2tf(b1v.y);
        Bs[p][brow + 8][bcol + 2] = f2tf(b1v.z); Bs[p][brow + 8][bcol + 3] = f2tf(b1v.w);
    };
    auto compute = [&](int p) {
#pragma unroll
        for (int k8 = 0; k8 < 2; k8++) {
            const int kb = k8 * 8;
            unsigned af[2][4], bf[8][2];
#pragma unroll
            for (int mi = 0; mi < 2; mi++) {
                int r = wm * 32 + mi * 16 + (lane >> 2);
                af[mi][0] = As[p][r][kb + (lane & 3)];
                af[mi][1] = As[p][r + 8][kb + (lane & 3)];
                af[mi][2] = As[p][r][kb + (lane & 3) + 4];
                af[mi][3] = As[p][r + 8][kb + (lane & 3) + 4];
            }
#pragma unroll
            for (int ni = 0; ni < 8; ni++) {
                int c = wn * 64 + ni * 8 + (lane >> 2);
                bf[ni][0] = Bs[p][kb + (lane & 3)][c];
                bf[ni][1] = Bs[p][kb + (lane & 3) + 4][c];
            }
#pragma unroll
            for (int mi = 0; mi < 2; mi++)
#pragma unroll
                for (int ni = 0; ni < 8; ni++) {
                    asm volatile(
                        "mma.sync.aligned.m16n8k8.row.col.f32.tf32.tf32.f32 "
                        "{%0,%1,%2,%3}, {%4,%5,%6,%7}, {%8,%9}, {%0,%1,%2,%3};"
                        : "+f"(acc[mi][ni][0]), "+f"(acc[mi][ni][1]),
                          "+f"(acc[mi][ni][2]), "+f"(acc[mi][ni][3])
                        : "r"(af[mi][0]), "r"(af[mi][1]), "r"(af[mi][2]), "r"(af[mi][3]),
                          "r"(bf[ni][0]), "r"(bf[ni][1]));
                }
        }
    };

    loadT(0); stage(0); __syncthreads();
    int buf = 0;
    for (int k0 = 16; k0 < K; k0 += 16) {
        loadT(k0);
        compute(buf);
        stage(buf ^ 1);
        __syncthreads();
        buf ^= 1;
    }
    compute(buf);

#pragma unroll
    for (int mi = 0; mi < 2; mi++) {
        int r = m0 + wm * 32 + mi * 16 + (lane >> 2);
        int r0 = PERMUTE ? ((r & (B_ - 1)) * T_ + (r >> 4)) : r;
        int r8 = r + 8;
        int r1 = PERMUTE ? ((r8 & (B_ - 1)) * T_ + (r8 >> 4)) : r8;
#pragma unroll
        for (int ni = 0; ni < 8; ni++) {
            int c = n0 + wn * 64 + ni * 8 + (lane & 3) * 2;
            if (c < ncols) {
                float bc0 = bias[c], bc1 = bias[c + 1];
                C[(size_t)r0 * ldc + c]     = acc[mi][ni][0] + bc0;
                C[(size_t)r0 * ldc + c + 1] = acc[mi][ni][1] + bc1;
                C[(size_t)r1 * ldc + c]     = acc[mi][ni][2] + bc0;
                C[(size_t)r1 * ldc + c + 1] = acc[mi][ni][3] + bc1;
            }
        }
    }
}

// ---------------- tf32 GEMM, 256x128 tile, 256 threads (vocab) --------------
// Halves B re-reads vs the 128-row tile (4x instead of 8x over W_out).
__global__ __launch_bounds__(256, 1)
void mma_gemm256_kernel(const float* __restrict__ A, int lda,
                        const float* __restrict__ Bm, int ldb,
                        float* __restrict__ C, int ldc,
                        const float* __restrict__ bias, int K, int ncols)
{
    extern __shared__ unsigned char gsm[];
    unsigned (*As)[256][20] = (unsigned(*)[256][20])gsm;              // m-major
    unsigned (*Bs)[16][136] = (unsigned(*)[16][136])(gsm + G2_AS_BYTES);

    const int tid = threadIdx.x;
    const int wid = tid >> 5, lane = tid & 31;
    const int wm = wid & 3, wn = wid >> 2;          // warps 4(M) x 2(N)
    const int m0 = blockIdx.y * 256, n0 = blockIdx.x * 128;

    const int arow = tid >> 2;                      // 0..63 (+64,+128,+192)
    const int acol = (tid & 3) * 4;
    const int brow = tid >> 5;                      // 0..7 (+8)
    const int bcol = lane * 4;
    int colb = n0 + bcol;
    if (colb > ncols - 4) colb = ncols - 4;

    float acc[4][8][4];
#pragma unroll
    for (int mi = 0; mi < 4; mi++)
#pragma unroll
        for (int ni = 0; ni < 8; ni++)
#pragma unroll
            for (int u = 0; u < 4; u++) acc[mi][ni][u] = 0.0f;

    float4 av[4];
    float4 b0v, b1v;

    auto loadT = [&](int k0) {
#pragma unroll
        for (int h = 0; h < 4; h++)
            av[h] = *reinterpret_cast<const float4*>(
                &A[(size_t)(m0 + h * 64 + arow) * lda + k0 + acol]);
        b0v = *reinterpret_cast<const float4*>(&Bm[(size_t)(k0 + brow) * ldb + colb]);
        b1v = *reinterpret_cast<const float4*>(&Bm[(size_t)(k0 + brow + 8) * ldb + colb]);
    };
    auto stage = [&](int p) {
#pragma unroll
        for (int h = 0; h < 4; h++) {
            const int r = h * 64 + arow;
            As[p][r][acol + 0] = f2tf(av[h].x); As[p][r][acol + 1] = f2tf(av[h].y);
            As[p][r][acol + 2] = f2tf(av[h].z); As[p][r][acol + 3] = f2tf(av[h].w);
        }
        Bs[p][brow][bcol + 0] = f2tf(b0v.x); Bs[p][brow][bcol + 1] = f2tf(b0v.y);
        Bs[p][brow][bcol + 2] = f2tf(b0v.z); Bs[p][brow][bcol + 3] = f2tf(b0v.w);
        Bs[p][brow + 8][bcol + 0] = f2tf(b1v.x); Bs[p][brow + 8][bcol + 1] = f2tf(b1v.y);
        Bs[p][brow + 8][bcol + 2] = f2tf(b1v.z); Bs[p][brow + 8][bcol + 3] = f2tf(b1v.w);
    };
    auto compute = [&](int p) {
#pragma unroll
        for (int k8 = 0; k8 < 2; k8++) {
            const int kb = k8 * 8;
            unsigned af[4][4], bf[8][2];
#pragma unroll
            for (int mi = 0; mi < 4; mi++) {
                int r = wm * 64 + mi * 16 + (lane >> 2);
                af[mi][0] = As[p][r][kb + (lane & 3)];
                af[mi][1] = As[p][r + 8][kb + (lane & 3)];
                af[mi][2] = As[p][r][kb + (lane & 3) + 4];
                af[mi][3] = As[p][r + 8][kb + (lane & 3) + 4];
            }
#pragma unroll
            for (int ni = 0; ni < 8; ni++) {
                int c = wn * 64 + ni * 8 + (lane >> 2);
                bf[ni][0] = Bs[p][kb + (lane & 3)][c];
                bf[ni][1] = Bs[p][kb + (lane & 3) + 4][c];
            }
#pragma unroll
            for (int mi = 0; mi < 4; mi++)
#pragma unroll
                for (int ni = 0; ni < 8; ni++) {
                    asm volatile(
                        "mma.sync.aligned.m16n8k8.row.col.f32.tf32.tf32.f32 "
                        "{%0,%1,%2,%3}, {%4,%5,%6,%7}, {%8,%9}, {%0,%1,%2,%3};"
                        : "+f"(acc[mi][ni][0]), "+f"(acc[mi][ni][1]),
                          "+f"(acc[mi][ni][2]), "+f"(acc[mi][ni][3])
                        : "r"(af[mi][0]), "r"(af[mi][1]), "r"(af[mi][2]), "r"(af[mi][3]),
                          "r"(bf[ni][0]), "r"(bf[ni][1]));
                }
        }
    };

    loadT(0); stage(0); __syncthreads();
    int buf = 0;
    for (int k0 = 16; k0 < K; k0 += 16) {
        loadT(k0);
        compute(buf);
        stage(buf ^ 1);
        __syncthreads();
        buf ^= 1;
    }
    compute(buf);

#pragma unroll
    for (int mi = 0; mi < 4; mi++) {
        int r = m0 + wm * 64 + mi * 16 + (lane >> 2);
        int r0 = (r & (B_ - 1)) * T_ + (r >> 4);        // PERMUTE (vocab only)
        int r8 = r + 8;
        int r1 = (r8 & (B_ - 1)) * T_ + (r8 >> 4);
#pragma unroll
        for (int ni = 0; ni < 8; ni++) {
            int c = n0 + wn * 64 + ni * 8 + (lane & 3) * 2;
            if (c < ncols) {
                float bc0 = bias[c], bc1 = bias[c + 1];
                C[(size_t)r0 * ldc + c]     = acc[mi][ni][0] + bc0;
                C[(size_t)r0 * ldc + c + 1] = acc[mi][ni][1] + bc1;
                C[(size_t)r1 * ldc + c]     = acc[mi][ni][2] + bc0;
                C[(size_t)r1 * ldc + c + 1] = acc[mi][ni][3] + bc1;
            }
        }
    }
}

// ---------------- grid-wide barrier (atomic-free, flag-per-block) -----------
__device__ __forceinline__ void gsync(unsigned target) {
    __syncthreads();
    if (blockIdx.x == 0) {
        // detector: threads 1..147 each watch one block's flag (parallel polls)
        if (threadIdx.x > 0 && threadIdx.x < NBLK) {
            while ((unsigned)g_arrive[threadIdx.x] < target) __nanosleep(64);
        }
        __syncthreads();
        if (threadIdx.x == 0) { __threadfence(); g_barsense = target; }
    } else {
        if (threadIdx.x == 0) {
            __threadfence();
            g_arrive[blockIdx.x] = (int)target;      // plain store, no atomic
            while (g_barsense < target) __nanosleep(64);
            __threadfence();
        }
    }
    __syncthreads();
}

// ---------------- persistent recurrence kernel (512 thr, 16 warps/SM) -------
__global__ __launch_bounds__(512, 1)
void recur_kernel(const float* __restrict__ Whh,
                  const float* __restrict__ Ws,
                  const float* __restrict__ bs,
                  const float* __restrict__ bhh)
{
    extern __shared__ unsigned char dsm[];
    unsigned* wt_all = (unsigned*)dsm;
    float*    hs     = (float*)(dsm + HS_OFF);
    unsigned (*sa)[136]     = (unsigned(*)[136])(dsm + SA_OFF);
    float    (*part)[16][66] = (float(*)[16][66])(dsm + PART_OFF);
    float    (*e_sh)[65]    = (float(*)[65])(dsm + E_OFF);
    float*    s2            = (float*)(dsm + SA_OFF);          // phase B alias
    float    (*redp)[64]    = (float(*)[64])(dsm + SA_OFF + 2048);

    const int tid = threadIdx.x;
    const int bid = blockIdx.x;
    const int lane = tid & 31, wid = tid >> 5;

    // ---- W_hh tile ownership: same q for all of this block's tiles ----
    const int q = bid & 7;
    const int gidx = bid >> 3;
    const int gcount = (q < 4) ? 19 : 18;
    const int c0t = gidx * 48 / gcount;
    const int c1t = (gidx + 1) * 48 / gcount;
    const int ntile = c1t - c0t;                     // 2 or 3

    // ---- Hih column ownership (independent contiguous map) ----
    const int c0h = (G3_ * bid) / NBLK, c1h = (G3_ * (bid + 1)) / NBLK;
    const int ncolsh = c1h - c0h;                    // 20 or 21

    // ---- preload W_hh tiles (tf32) ----
    for (int j = 0; j < ntile; j++) {
        const int c = c0t + j;
        const int rr = tid >> 4, c4 = (tid & 15) * 4;   // rr 0..31
        unsigned* wt = wt_all + j * WT_ELEMS;
#pragma unroll
        for (int p = 0; p < 4; p++) {
            int row = p * 32 + rr;
            float4 v = *reinterpret_cast<const float4*>(
                &Whh[(size_t)(q * 128 + row) * G3_ + c * 64 + c4]);
            wt[row * 72 + c4 + 0] = f2tf(v.x);
            wt[row * 72 + c4 + 1] = f2tf(v.y);
            wt[row * 72 + c4 + 2] = f2tf(v.z);
            wt[row * 72 + c4 + 3] = f2tf(v.w);
        }
    }
    // ---- preload Hih columns (fp32, transposed) ----
    for (int p = tid; p < 1024 * ncolsh; p += 512) {
        int row = p / ncolsh, cl = p - row * ncolsh;
        hs[cl * HSPITCH + row] = g_Hih[(size_t)row * G3_ + c0h + cl];
    }
    __syncthreads();

    const int half = wid >> 3;          // 0/1: which concurrent tile
    const int hwid = wid & 7;           // warp within the 8-warp half
    const int wk = hwid >> 2, wn = hwid & 3;

    unsigned bar = 0;
    for (int i = 0; i < T_; i++) {
        // ---- phase A: stage s (q slice) once ----
        {
            const int b = tid >> 5, c4 = (tid & 31) * 4;
            float4 v = *reinterpret_cast<const float4*>(&g_s[b * H_ + q * 128 + c4]);
            sa[b][c4 + 0] = f2tf(v.x); sa[b][c4 + 1] = f2tf(v.y);
            sa[b][c4 + 2] = f2tf(v.z); sa[b][c4 + 3] = f2tf(v.w);
        }
        __syncthreads();
        // ---- phase A: s@W_hh, two tiles at a time ----
        for (int jj = 0; jj < ntile; jj += 2) {
            const int nt = (ntile - jj < 2) ? (ntile - jj) : 2;
            const int j = jj + half;
            float acc[2][4];
#pragma unroll
            for (int ni = 0; ni < 2; ni++)
#pragma unroll
                for (int u = 0; u < 4; u++) acc[ni][u] = 0.0f;
            if (half < nt) {
                const unsigned* wt = wt_all + j * WT_ELEMS;
#pragma unroll
                for (int k8 = 0; k8 < 8; k8++) {
                    const int kb = wk * 64 + k8 * 8;
                    unsigned af[4];
                    af[0] = sa[lane >> 2][kb + (lane & 3)];
                    af[1] = sa[(lane >> 2) + 8][kb + (lane & 3)];
                    af[2] = sa[lane >> 2][kb + (lane & 3) + 4];
                    af[3] = sa[(lane >> 2) + 8][kb + (lane & 3) + 4];
#pragma unroll
                    for (int ni = 0; ni < 2; ni++) {
                        const int cc = wn * 16 + ni * 8 + (lane >> 2);
                        unsigned bf0 = wt[(kb + (lane & 3)) * 72 + cc];
                        unsigned bf1 = wt[(kb + (lane & 3) + 4) * 72 + cc];
                        asm volatile(
                            "mma.sync.aligned.m16n8k8.row.col.f32.tf32.tf32.f32 "
                            "{%0,%1,%2,%3}, {%4,%5,%6,%7}, {%8,%9}, {%0,%1,%2,%3};"
                            : "+f"(acc[ni][0]), "+f"(acc[ni][1]),
                              "+f"(acc[ni][2]), "+f"(acc[ni][3])
                            : "r"(af[0]), "r"(af[1]), "r"(af[2]), "r"(af[3]),
                              "r"(bf0), "r"(bf1));
                    }
                }
            }
            __syncthreads();
            if (half < nt && wk == 1) {
#pragma unroll
                for (int ni = 0; ni < 2; ni++) {
                    const int r = lane >> 2, cc = wn * 16 + ni * 8 + (lane & 3) * 2;
                    part[half][r][cc]         = acc[ni][0];
                    part[half][r][cc + 1]     = acc[ni][1];
                    part[half][r + 8][cc]     = acc[ni][2];
                    part[half][r + 8][cc + 1] = acc[ni][3];
                }
            }
            __syncthreads();
            if (half < nt && wk == 0) {
                const int c = c0t + j;
#pragma unroll
                for (int ni = 0; ni < 2; ni++) {
                    const int r = lane >> 2, cc = wn * 16 + ni * 8 + (lane & 3) * 2;
                    const int gc = c * 64 + cc;
                    g_gpart[(size_t)(q * 16 + r) * G3_ + gc] =
                        acc[ni][0] + part[half][r][cc];
                    g_gpart[(size_t)(q * 16 + r) * G3_ + gc + 1] =
                        acc[ni][1] + part[half][r][cc + 1];
                    g_gpart[(size_t)(q * 16 + r + 8) * G3_ + gc] =
                        acc[ni][2] + part[half][r + 8][cc];
                    g_gpart[(size_t)(q * 16 + r + 8) * G3_ + gc + 1] =
                        acc[ni][3] + part[half][r + 8][cc + 1];
                }
            }
            __syncthreads();
        }
        // ---- phase A: softmax (first 256 threads; identical arithmetic) ----
        if (tid < 256) {
            const int b2 = (tid >> 5) * 2 + (lane >> 4);
            const int j0 = (lane & 15) * 4;
            float a[4];
#pragma unroll
            for (int u = 0; u < 4; u++) {
                int jx = j0 + u;
                float v = bs[jx] + g_hemb[(b2 * T_ + i) * T_ + jx];
#pragma unroll
                for (int kc = 0; kc < 2; kc++) v += g_alignpart[kc][b2][jx];
                a[u] = tanhf(v);
            }
            float m = fmaxf(fmaxf(a[0], a[1]), fmaxf(a[2], a[3]));
#pragma unroll
            for (int o = 8; o > 0; o >>= 1)
                m = fmaxf(m, __shfl_xor_sync(0xffffffffu, m, o));
            float ex[4], ssum = 0.0f;
#pragma unroll
            for (int u = 0; u < 4; u++) { ex[u] = __expf(a[u] - m); ssum += ex[u]; }
#pragma unroll
            for (int o = 8; o > 0; o >>= 1)
                ssum += __shfl_xor_sync(0xffffffffu, ssum, o);
            float inv = 1.0f / ssum;
#pragma unroll
            for (int u = 0; u < 4; u++) {
                e_sh[b2][j0 + u] = ex[u] * inv;
                if (bid == 0) g_E[(i * B_ + b2) * T_ + j0 + u] = ex[u] * inv;
            }
        }
        __syncthreads();
        // ---- phase A: gi = e @ Hih (smem Hih) ----
        for (int p = tid; p < 16 * ncolsh; p += 512) {
            const int b = p / ncolsh, cl = p - b * ncolsh;
            const float* hrow = hs + cl * HSPITCH + b * 64;
            float a0 = 0.0f, a1 = 0.0f;
#pragma unroll
            for (int t = 0; t < 64; t += 4) {
                float2 h0 = *reinterpret_cast<const float2*>(hrow + t);
                float2 h1 = *reinterpret_cast<const float2*>(hrow + t + 2);
                a0 += e_sh[b][t] * h0.x + e_sh[b][t + 1] * h0.y;
                a1 += e_sh[b][t + 2] * h1.x + e_sh[b][t + 3] * h1.y;
            }
            g_gpart[(size_t)(8 * 16 + b) * G3_ + c0h + cl] = a0 + a1;
        }
        gsync(++bar);
        // ---- phase B: GRU pointwise + s@W_s (32 blocks x 512 k) ----
        if (bid < 32) {
            const int b = bid >> 1, hf = bid & 1;
            const int k = hf * 512 + tid;

            float gr = bhh[k], gz = bhh[H_ + k], hn = bhh[2 * H_ + k];
#pragma unroll
            for (int qq = 0; qq < 8; qq++) {
                const float* P = g_gpart + (size_t)(qq * 16 + b) * G3_;
                gr += P[k]; gz += P[H_ + k]; hn += P[2 * H_ + k];
            }
            const float* P8 = g_gpart + (size_t)(8 * 16 + b) * G3_;
            gr += P8[k]; gz += P8[H_ + k];
            float inn = P8[2 * H_ + k];

            float r = 1.0f / (1.0f + __expf(-gr));
            float z = 1.0f / (1.0f + __expf(-gz));
            float n = tanhf(inn + r * hn);
            float sold = g_s[b * H_ + k];
            float snew = (1.0f - z) * n + z * sold;
            g_s[b * H_ + k] = snew;
            g_cat[(size_t)(i * B_ + b) * CAT_ + k] = snew;

            s2[tid] = snew;
            __syncthreads();
            const int j = tid & 63, sub = tid >> 6;     // 8 subs x 64 j
            float a = 0.0f;
#pragma unroll 8
            for (int kk = 0; kk < 64; kk++)
                a += s2[sub * 64 + kk] *
                     Ws[(size_t)(hf * 512 + sub * 64 + kk) * T_ + j];
            redp[sub][j] = a;
            __syncthreads();
            if (tid < 64)
                g_alignpart[hf][b][tid] =
                    redp[0][tid] + redp[1][tid] + redp[2][tid] + redp[3][tid] +
                    redp[4][tid] + redp[5][tid] + redp[6][tid] + redp[7][tid];
        }
        gsync(++bar);
    }
}

// ---------------- batched context: c[i,b,:] = e[i,b,:] @ h[b] ---------------
__global__ __launch_bounds__(128)
void ctx_kernel(const float* __restrict__ h)
{
    const int b = blockIdx.x, dc = blockIdx.y, tid = threadIdx.x;
    __shared__ float sh_h[T_][128];
    __shared__ float e_sh[T_];
    const int dbase = dc * 128;
    for (int t = 0; t < T_; t++)
        sh_h[t][tid] = h[(size_t)(b * T_ + t) * D_ + dbase + tid];
    __syncthreads();
    for (int i = 0; i < T_; i++) {
        if (tid < 64) e_sh[tid] = g_E[(i * B_ + b) * T_ + tid];
        __syncthreads();
        float acc = 0.0f;
#pragma unroll 8
        for (int t = 0; t < T_; t++) acc += e_sh[t] * sh_h[t][tid];
        g_cat[(size_t)(i * B_ + b) * CAT_ + H_ + EMB_ + dbase + tid] = acc;
        __syncthreads();
    }
}

// ---------------- maxout (materialized: halves vocab-GEMM A traffic) --------
__global__ void maxout_kernel()
{
    const int idx = blockIdx.x * blockDim.x + threadIdx.x;
    const int r = idx >> 10, m = idx & (MO_ - 1);
    g_tmax[idx] = fmaxf(g_tt[(size_t)r * 2 * MO_ + m],
                        g_tt[(size_t)r * 2 * MO_ + MO_ + m]);
}

// ---------------------------------------------------------------------------
extern "C" void kernel_launch(void* const* d_in, const int* in_sizes, int n_in,
                              void* d_out, int out_size)
{
    (void)in_sizes; (void)n_in; (void)out_size;
    const float* h     = (const float*)d_in[0];
    const float* W_h   = (const float*)d_in[1];
    const float* b_h   = (const float*)d_in[2];
    const float* W_s   = (const float*)d_in[3];
    const float* b_s   = (const float*)d_in[4];
    const float* W_ih  = (const float*)d_in[5];
    const float* b_ih  = (const float*)d_in[6];
    const float* W_hh  = (const float*)d_in[7];
    const float* b_hh  = (const float*)d_in[8];
    const float* W_emb = (const float*)d_in[9];
    const float* b_emb = (const float*)d_in[10];
    const float* W_t   = (const float*)d_in[11];
    const float* b_t   = (const float*)d_in[12];
    const float* W_out = (const float*)d_in[13];
    const float* b_out = (const float*)d_in[14];
    float* out = (float*)d_out;

    float *p_hemb, *p_Hih, *p_cat, *p_tt, *p_tmax;
    cudaGetSymbolAddress((void**)&p_hemb, g_hemb);
    cudaGetSymbolAddress((void**)&p_Hih,  g_Hih);
    cudaGetSymbolAddress((void**)&p_cat,  g_cat);
    cudaGetSymbolAddress((void**)&p_tt,   g_tt);
    cudaGetSymbolAddress((void**)&p_tmax, g_tmax);

    static int smem_set = 0;
    if (!smem_set) {
        cudaFuncSetAttribute(recur_kernel,
                             cudaFuncAttributeMaxDynamicSharedMemorySize,
                             DSMEM_BYTES);
        cudaFuncSetAttribute(mma_gemm256_kernel,
                             cudaFuncAttributeMaxDynamicSharedMemorySize,
                             G2_SMEM);
        smem_set = 1;
    }

    init_kernel<<<(B_ * H_ + 255) / 256, 256>>>();

    // Precompute: h_emb = h@W_h+b_h (N=64, guarded) ; Hih = h@W_ih+b_ih
    mma_gemm_kernel<false><<<dim3(1, (B_ * T_) / 128), 256>>>(
        h, D_, W_h, T_, p_hemb, T_, b_h, D_, T_);
    mma_gemm_kernel<false><<<dim3(G3_ / 128, (B_ * T_) / 128), 256>>>(
        h, D_, W_ih, G3_, p_Hih, G3_, b_ih, D_, G3_);

    // Entire 64-step recurrence in ONE persistent cooperative kernel
    recur_kernel<<<NBLK, 512, DSMEM_BYTES>>>(W_hh, W_s, b_s, b_hh);

    // Batched epilogue
    ctx_kernel<<<dim3(B_, D_ / 128), 128>>>(h);
    mma_gemm_kernel<false><<<dim3(EMB_ / 128, (T_ * B_) / 128), 256>>>(
        p_cat, CAT_, W_emb, EMB_, p_cat + H_, CAT_, b_emb, H_, EMB_);
    mma_gemm_kernel<false><<<dim3(2 * MO_ / 128, (T_ * B_) / 128), 256>>>(
        p_cat, CAT_, W_t, 2 * MO_, p_tt, 2 * MO_, b_t, CAT_, 2 * MO_);
    maxout_kernel<<<(T_ * B_ * MO_) / 256, 256>>>();
    // Vocab GEMM: 256x128 tiles, permuted rows
    mma_gemm256_kernel<<<dim3(V_ / 128, (T_ * B_) / 256), 256, G2_SMEM>>>(
        p_tmax, MO_, W_out, V_, out, V_, b_out, MO_, V_);
}